// round 10
// baseline (speedup 1.0000x reference)
#include <cuda_runtime.h>
#include <cuda_fp16.h>
#include <mma.h>
#include <cstdint>
#include <cmath>

using namespace nvcuda;

#define NTOK   262152
#define CDIM   256
#define NSETS  7282
#define SETSZ  36
#define NHEAD  8
#define DHEAD  32
#define DFFN   1024

// ---------------------------------------------------------------------------
// Workspace (single symbol, < 4GB). ~2.0 GB.
// Aliases (stream-order safe):
//   x1 (fp32) aliases qkph (fp16 512/tok, same 537MB... both NTOK*1024B)
//   vh == oh == ffh (fp16, each dead before next writer)
//   x1b == qkb, attnb == featb
// ---------------------------------------------------------------------------
#define SZ_C   ((size_t)NTOK * 256 * 4)     // 268MB (fp32 256/tok)
#define SZ_H   ((size_t)NTOK * 256 * 2)     // 134MB (fp16 256/tok)
#define OFF_X    ((size_t)0)
#define OFF_RES  (OFF_X    + SZ_C)
#define OFF_QKPH (OFF_RES  + SZ_C)          // fp16 NTOK x 512 == SZ_C bytes; x1 fp32 aliases
#define OFF_VOF  (OFF_QKPH + SZ_C)          // fp16 vh / oh / ffh
#define OFF_QKB  (OFF_VOF  + SZ_H)          // fp16 (x1b aliases)
#define OFF_FEB  (OFF_QKB  + SZ_H)          // fp16 (attnb aliases)
#define OFF_HB   (OFF_FEB  + SZ_H)          // fp16 NTOK x 1024
#define OFF_WIP  (OFF_HB   + (size_t)NTOK * 1024 * 2)
#define OFF_WOW  (OFF_WIP + (size_t)4*768*256*2)
#define OFF_WL1  (OFF_WOW + (size_t)4*256*256*2)
#define OFF_WL2  (OFF_WL1 + (size_t)4*1024*256*2)
#define WS_TOT   (OFF_WL2 + (size_t)4*256*1024*2)

__device__ __align__(256) char g_ws[WS_TOT];
__device__ int g_mask_mode;

// ---------------------------------------------------------------------------
// Helpers
// ---------------------------------------------------------------------------
__device__ __forceinline__ uint32_t smem_u32(const void* p) {
    uint32_t a;
    asm("{ .reg .u64 t; cvta.to.shared.u64 t, %1; cvt.u32.u64 %0, t; }"
        : "=r"(a) : "l"(p));
    return a;
}
__device__ __forceinline__ void cp16(uint32_t dst, const void* src, int sz) {
    asm volatile("cp.async.cg.shared.global [%0], [%1], 16, %2;"
                 :: "r"(dst), "l"(src), "r"(sz) : "memory");
}
#define CP_COMMIT() asm volatile("cp.async.commit_group;" ::: "memory")
#define CP_WAIT1()  asm volatile("cp.async.wait_group 1;" ::: "memory")
#define CP_WAIT0()  asm volatile("cp.async.wait_group 0;" ::: "memory")

__device__ __forceinline__ uint32_t pack2h(float a, float b) {
    __half2 h;
    h.x = __float2half_rn(a); h.y = __float2half_rn(b);
    return *reinterpret_cast<uint32_t*>(&h);
}
__device__ __forceinline__ void write4h(__half* p, float4 v) {
    *(uint2*)p = make_uint2(pack2h(v.x, v.y), pack2h(v.z, v.w));
}
__device__ __forceinline__ float4 read4h(const __half* p) {
    const __half2* h = (const __half2*)p;
    float2 a = __half22float2(h[0]);
    float2 b = __half22float2(h[1]);
    return make_float4(a.x, a.y, b.x, b.y);
}

// ---------------------------------------------------------------------------
// Weight converter: fp32 -> plain fp16
// ---------------------------------------------------------------------------
__global__ __launch_bounds__(256) void wconv_kernel(
    const float* __restrict__ src, __half* __restrict__ dst, int n)
{
    int idx = blockIdx.x * 256 + threadIdx.x;
    if (idx >= n) return;
    dst[idx] = __float2half_rn(src[idx]);
}

// ---------------------------------------------------------------------------
// Mask dtype detector
// ---------------------------------------------------------------------------
__global__ void detect_mask_kernel(const unsigned int* __restrict__ w, int nwords)
{
    __shared__ int f32f, u8f;
    if (threadIdx.x == 0) { f32f = 0; u8f = 0; }
    __syncthreads();
    int lf = 0, lu = 0;
    for (int i = threadIdx.x; i < nwords; i += blockDim.x) {
        unsigned int x = w[i];
        if (x == 0x3F800000u) lf = 1;
        else if (x > 1u)      lu = 1;
    }
    if (lf) f32f = 1;
    if (lu) u8f = 1;
    __syncthreads();
    if (threadIdx.x == 0) g_mask_mode = f32f ? 2 : (u8f ? 1 : 0);
}

// ---------------------------------------------------------------------------
// Gather: fp16 qk (= x[inds]+pos[inds]) and feat (= x[inds])
// ---------------------------------------------------------------------------
__global__ __launch_bounds__(256) void gather_kernel(
    const float* __restrict__ x, const float* __restrict__ pos,
    const int* __restrict__ inds, __half* __restrict__ qkb,
    __half* __restrict__ featb)
{
    int idx = blockIdx.x * 256 + threadIdx.x;
    if (idx >= NTOK * 64) return;
    int j  = idx >> 6;
    int c4 = idx & 63;
    int t  = inds[j];
    float4 xv = ((const float4*)x)  [(size_t)t * 64 + c4];
    float4 pv = ((const float4*)pos)[(size_t)t * 64 + c4];
    float4 q  = make_float4(xv.x + pv.x, xv.y + pv.y, xv.z + pv.z, xv.w + pv.w);
    write4h(featb + (size_t)j * 256 + c4 * 4, xv);
    write4h(qkb   + (size_t)j * 256 + c4 * 4, q);
}

// ---------------------------------------------------------------------------
// fp16 GEMM: C[m,n] = A[m,:] . W[n,:] + bias[n] (+GELU), fp32 acc, fp16 out.
// CTA 128x256, BK=64, 3-stage cp.async, 16 warps (4x4) of 32x64 each.
// Requires N % 256 == 0, KA % 64 == 0.
// ---------------------------------------------------------------------------
#define STAGE_A  18432                 // 128 rows x 144B
#define STAGE_W  36864                 // 256 rows x 144B
#define STAGE_T  (STAGE_A + STAGE_W)   // 55296
#define GSMEM    (3 * STAGE_T)         // 165888; epilogue scratch aliases

__global__ __launch_bounds__(512, 1) void gemm_fp16_kernel(
    const __half* __restrict__ A, int KA,
    const __half* __restrict__ W, const float* __restrict__ bias,
    __half* __restrict__ C, int M, int N, int act)
{
    extern __shared__ char smem[];
    const uint32_t sb = smem_u32(smem);
    const int tid  = threadIdx.x;
    const int wid  = tid >> 5;
    const int lane = tid & 31;
    const int wr   = wid >> 2;   // 0..3 (rows of 32)
    const int wc   = wid & 3;    // 0..3 (cols of 64)
    const int m0   = blockIdx.y * 128;
    const int n0   = blockIdx.x * 256;
    const int NC   = KA >> 6;

    wmma::fragment<wmma::accumulator, 16, 16, 16, float> acc[2][4];
#pragma unroll
    for (int i = 0; i < 2; i++)
#pragma unroll
        for (int j = 0; j < 4; j++) wmma::fill_fragment(acc[i][j], 0.0f);

    auto load_stage = [&](int slot, int c) {
        const int k0 = c << 6;
        const uint32_t base = sb + slot * STAGE_T;
#pragma unroll
        for (int it = 0; it < 2; it++) {          // A: 128 rows x 8 chunks
            int i  = tid + it * 512;
            int r  = i >> 3;
            int ch = i & 7;
            int gr = m0 + r;
            const __half* sa =
                A + (size_t)(gr < M ? gr : M - 1) * KA + k0 + ch * 8;
            cp16(base + r * 144 + ch * 16, sa, gr < M ? 16 : 0);
        }
#pragma unroll
        for (int it = 0; it < 4; it++) {          // W: 256 rows x 8 chunks
            int i  = tid + it * 512;
            int r  = i >> 3;
            int ch = i & 7;
            const __half* sw = W + (size_t)(n0 + r) * KA + k0 + ch * 8;
            cp16(base + STAGE_A + r * 144 + ch * 16, sw, 16);
        }
    };

    load_stage(0, 0); CP_COMMIT();
    load_stage(1, 1); CP_COMMIT();

    for (int c = 0; c < NC; c++) {
        CP_WAIT1();
        __syncthreads();
        const int slot = c % 3;
        const __half* sA = (const __half*)(smem + slot * STAGE_T);
        const __half* sB = (const __half*)(smem + slot * STAGE_T + STAGE_A);
#pragma unroll
        for (int kk = 0; kk < 4; kk++) {
            wmma::fragment<wmma::matrix_a, 16, 16, 16, __half,
                           wmma::row_major> a[2];
#pragma unroll
            for (int i = 0; i < 2; i++)
                wmma::load_matrix_sync(a[i], sA + (wr * 32 + i * 16) * 72 + kk * 16, 72);
#pragma unroll
            for (int j = 0; j < 4; j++) {
                wmma::fragment<wmma::matrix_b, 16, 16, 16, __half,
                               wmma::col_major> b;
                wmma::load_matrix_sync(b, sB + (wc * 64 + j * 16) * 72 + kk * 16, 72);
#pragma unroll
                for (int i = 0; i < 2; i++)
                    wmma::mma_sync(acc[i][j], a[i], b, acc[i][j]);
            }
        }
        __syncthreads();
        const int cn = c + 2;
        if (cn < NC) load_stage(cn % 3, cn);
        CP_COMMIT();
    }

    CP_WAIT0();
    __syncthreads();

    // epilogue: scratch aliases stage smem (16 warps x 16x24 floats = 96KB)
    float* scr = (float*)smem + wid * 16 * 24;
#pragma unroll
    for (int i = 0; i < 2; i++)
#pragma unroll
        for (int j = 0; j < 4; j++) {
            wmma::store_matrix_sync(scr, acc[i][j], 24, wmma::mem_row_major);
            __syncwarp();
            int r  = lane >> 1;
            int ch = (lane & 1) * 8;
            int gr = m0 + wr * 32 + i * 16 + r;
            int gc = n0 + wc * 64 + j * 16 + ch;
            if (gr < M) {
                float4 b0 = *(const float4*)(bias + gc);
                float4 b1 = *(const float4*)(bias + gc + 4);
                float v[8];
                v[0] = scr[r * 24 + ch + 0] + b0.x;
                v[1] = scr[r * 24 + ch + 1] + b0.y;
                v[2] = scr[r * 24 + ch + 2] + b0.z;
                v[3] = scr[r * 24 + ch + 3] + b0.w;
                v[4] = scr[r * 24 + ch + 4] + b1.x;
                v[5] = scr[r * 24 + ch + 5] + b1.y;
                v[6] = scr[r * 24 + ch + 6] + b1.z;
                v[7] = scr[r * 24 + ch + 7] + b1.w;
                if (act) {
#pragma unroll
                    for (int e = 0; e < 8; e++)
                        v[e] = 0.5f * v[e] *
                               (1.0f + erff(v[e] * 0.70710678118654752f));
                }
                __half* hp = C + (size_t)gr * N + gc;
                write4h(hp,     make_float4(v[0], v[1], v[2], v[3]));
                write4h(hp + 4, make_float4(v[4], v[5], v[6], v[7]));
            }
            __syncwarp();
        }
}

// ---------------------------------------------------------------------------
// Set attention (fp32 math, fp16 in/out)
// ---------------------------------------------------------------------------
__global__ __launch_bounds__(144, 1) void attn_kernel(
    const __half* __restrict__ qkp, const __half* __restrict__ vb,
    const void* __restrict__ maskp, int mask_off,
    __half* __restrict__ outb)
{
    const int s   = blockIdx.x;
    const int h0  = blockIdx.y * 4;
    const int tid = threadIdx.x;
    const int hl  = tid / SETSZ;
    const int l   = tid - hl * SETSZ;

    __shared__ float ks[4][SETSZ][DHEAD];
    __shared__ float vs[4][SETSZ][DHEAD];
    __shared__ float msk[SETSZ];

    if (tid < SETSZ) {
        int gi = mask_off + s * SETSZ + tid;
        int mode = g_mask_mode;
        bool m;
        if (mode == 0)      m = ((const int*)maskp)[gi] != 0;
        else if (mode == 1) m = ((const unsigned char*)maskp)[gi] != 0;
        else                m = ((const float*)maskp)[gi] != 0.0f;
        msk[tid] = m ? -INFINITY : 0.0f;
    }
    for (int idx = tid; idx < 4 * SETSZ * DHEAD; idx += 144) {
        int d  = idx & (DHEAD - 1);
        int m  = (idx >> 5) % SETSZ;
        int hh = idx / (DHEAD * SETSZ);
        size_t row = (size_t)s * SETSZ + m;
        ks[hh][m][d] = __half2float(qkp[row * 512 + 256 + (size_t)(h0 + hh) * DHEAD + d]);
        vs[hh][m][d] = __half2float(vb [row * 256 +       (size_t)(h0 + hh) * DHEAD + d]);
    }
    __syncthreads();

    float q[DHEAD];
    {
        const __half2* qr = (const __half2*)(qkp + ((size_t)s * SETSZ + l) * 512
                                             + (size_t)(h0 + hl) * DHEAD);
#pragma unroll
        for (int p = 0; p < 16; p++) {
            float2 f = __half22float2(qr[p]);
            q[2 * p] = f.x; q[2 * p + 1] = f.y;
        }
    }
    const float scale = 0.17677669529663687f;
    float sc[SETSZ];
    float mx = -INFINITY;
#pragma unroll
    for (int m = 0; m < SETSZ; m++) {
        float a = 0.f;
#pragma unroll
        for (int d = 0; d < DHEAD; d++) a += q[d] * ks[hl][m][d];
        a = a * scale + msk[m];
        sc[m] = a;
        mx = fmaxf(mx, a);
    }
    float den = 0.f;
#pragma unroll
    for (int m = 0; m < SETSZ; m++) { float e = expf(sc[m] - mx); sc[m] = e; den += e; }
    float inv = 1.0f / den;
    float o[DHEAD];
#pragma unroll
    for (int d = 0; d < DHEAD; d++) o[d] = 0.f;
#pragma unroll
    for (int m = 0; m < SETSZ; m++) {
        float a = sc[m] * inv;
#pragma unroll
        for (int d = 0; d < DHEAD; d++) o[d] += a * vs[hl][m][d];
    }
    __half* op = outb + ((size_t)s * SETSZ + l) * 256 + (size_t)(h0 + hl) * DHEAD;
#pragma unroll
    for (int p = 0; p < 8; p++)
        write4h(op + p * 4,
                make_float4(o[p*4], o[p*4+1], o[p*4+2], o[p*4+3]));
}

// ---------------------------------------------------------------------------
// LayerNorm helpers
// ---------------------------------------------------------------------------
__device__ __forceinline__ float wsum(float v)
{
#pragma unroll
    for (int o = 16; o > 0; o >>= 1) v += __shfl_xor_sync(0xffffffffu, v, o);
    return v;
}

__device__ __forceinline__ void ln8(float4& v0, float4& v1,
                                    const float* __restrict__ g,
                                    const float* __restrict__ b, int lane)
{
    float s  = v0.x + v0.y + v0.z + v0.w + v1.x + v1.y + v1.z + v1.w;
    float ss = v0.x*v0.x + v0.y*v0.y + v0.z*v0.z + v0.w*v0.w
             + v1.x*v1.x + v1.y*v1.y + v1.z*v1.z + v1.w*v1.w;
    s = wsum(s); ss = wsum(ss);
    float mean = s * (1.0f / 256.0f);
    float var  = ss * (1.0f / 256.0f) - mean * mean;
    float inv  = rsqrtf(fmaxf(var, 0.0f) + 1e-5f);
    float4 G0 = ((const float4*)g)[lane];
    float4 G1 = ((const float4*)g)[lane + 32];
    float4 B0 = ((const float4*)b)[lane];
    float4 B1 = ((const float4*)b)[lane + 32];
    v0.x = (v0.x - mean) * inv * G0.x + B0.x;
    v0.y = (v0.y - mean) * inv * G0.y + B0.y;
    v0.z = (v0.z - mean) * inv * G0.z + B0.z;
    v0.w = (v0.w - mean) * inv * G0.w + B0.w;
    v1.x = (v1.x - mean) * inv * G1.x + B1.x;
    v1.y = (v1.y - mean) * inv * G1.y + B1.y;
    v1.z = (v1.z - mean) * inv * G1.z + B1.z;
    v1.w = (v1.w - mean) * inv * G1.w + B1.w;
}

__device__ __forceinline__ float4 f4add(float4 a, float4 b)
{ return make_float4(a.x + b.x, a.y + b.y, a.z + b.z, a.w + b.w); }

// x1[t] = LN(x[t] + o[j]), t = inds[j]; o fp16; fp32 + fp16 outputs
__global__ __launch_bounds__(256) void ln1_scatter_kernel(
    const float* __restrict__ x, const __half* __restrict__ o,
    const int* __restrict__ inds, const float* __restrict__ g,
    const float* __restrict__ b, float* __restrict__ out,
    __half* __restrict__ outb)
{
    int w = (blockIdx.x << 3) + (threadIdx.x >> 5);
    if (w >= NTOK) return;
    int lane = threadIdx.x & 31;
    int t = inds[w];
    const float4* xr = (const float4*)(x + (size_t)t * 256);
    const __half* orr = o + (size_t)w * 256;
    float4 v0 = f4add(xr[lane],      read4h(orr + lane * 4));
    float4 v1 = f4add(xr[lane + 32], read4h(orr + 128 + lane * 4));
    ln8(v0, v1, g, b, lane);
    ((float4*)(out + (size_t)t * 256))[lane]      = v0;
    ((float4*)(out + (size_t)t * 256))[lane + 32] = v1;
    __half* ar = outb + (size_t)t * 256;
    write4h(ar + lane * 4,       v0);
    write4h(ar + 128 + lane * 4, v1);
}

// xio[t] = LN_enc( LN_2(x1 + ff) + xio ); ff fp16
__global__ __launch_bounds__(256) void ln2_enc_kernel(
    const float* __restrict__ x1, const __half* __restrict__ ff,
    float* __restrict__ xio,
    const float* __restrict__ g2, const float* __restrict__ b2,
    const float* __restrict__ ge, const float* __restrict__ be)
{
    int w = (blockIdx.x << 3) + (threadIdx.x >> 5);
    if (w >= NTOK) return;
    int lane = threadIdx.x & 31;
    const float4* r1 = (const float4*)(x1 + (size_t)w * 256);
    const __half* rf = ff + (size_t)w * 256;
    float4* rx = (float4*)(xio + (size_t)w * 256);
    float4 v0 = f4add(r1[lane],      read4h(rf + lane * 4));
    float4 v1 = f4add(r1[lane + 32], read4h(rf + 128 + lane * 4));
    ln8(v0, v1, g2, b2, lane);
    v0 = f4add(v0, rx[lane]);
    v1 = f4add(v1, rx[lane + 32]);
    ln8(v0, v1, ge, be, lane);
    rx[lane]      = v0;
    rx[lane + 32] = v1;
}

__global__ __launch_bounds__(256) void ln_res_kernel(
    const float* __restrict__ x, const float* __restrict__ r,
    const float* __restrict__ g, const float* __restrict__ b,
    float* __restrict__ out)
{
    int w = (blockIdx.x << 3) + (threadIdx.x >> 5);
    if (w >= NTOK) return;
    int lane = threadIdx.x & 31;
    const float4* xr = (const float4*)(x + (size_t)w * 256);
    const float4* rr = (const float4*)(r + (size_t)w * 256);
    float4 v0 = f4add(xr[lane],      rr[lane]);
    float4 v1 = f4add(xr[lane + 32], rr[lane + 32]);
    ln8(v0, v1, g, b, lane);
    ((float4*)(out + (size_t)w * 256))[lane]      = v0;
    ((float4*)(out + (size_t)w * 256))[lane + 32] = v1;
}

// ---------------------------------------------------------------------------
// Orchestration
// ---------------------------------------------------------------------------
extern "C" void kernel_launch(void* const* d_in, const int* in_sizes, int n_in,
                              void* d_out, int out_size)
{
    const float* src   = (const float*)d_in[0];
    const float* pos   = (const float*)d_in[1];
    const int*   inds  = (const int*)  d_in[2];
    const void*  masks =               d_in[3];
    const float* ipw   = (const float*)d_in[4];
    const float* ipb   = (const float*)d_in[5];
    const float* oww   = (const float*)d_in[6];
    const float* owb   = (const float*)d_in[7];
    const float* l1w   = (const float*)d_in[8];
    const float* l1b   = (const float*)d_in[9];
    const float* l2w   = (const float*)d_in[10];
    const float* l2b   = (const float*)d_in[11];
    const float* n1g   = (const float*)d_in[12];
    const float* n1b   = (const float*)d_in[13];
    const float* n2g   = (const float*)d_in[14];
    const float* n2b   = (const float*)d_in[15];
    const float* encg  = (const float*)d_in[16];
    const float* encb  = (const float*)d_in[17];
    const float* resg  = (const float*)d_in[18];
    const float* resb  = (const float*)d_in[19];
    float* outp = (float*)d_out;

    char* ws;
    cudaGetSymbolAddress((void**)&ws, g_ws);
    float*  x     = (float*)(ws + OFF_X);
    float*  res   = (float*)(ws + OFF_RES);
    __half* qkph  = (__half*)(ws + OFF_QKPH);
    float*  x1    = (float*)(ws + OFF_QKPH);   // alias: qkph dead after attn
    __half* vh    = (__half*)(ws + OFF_VOF);
    __half* oh    = (__half*)(ws + OFF_VOF);   // alias
    __half* ffh   = (__half*)(ws + OFF_VOF);   // alias
    __half* qkb   = (__half*)(ws + OFF_QKB);
    __half* x1b   = (__half*)(ws + OFF_QKB);   // alias
    __half* featb = (__half*)(ws + OFF_FEB);
    __half* attnb = (__half*)(ws + OFF_FEB);   // alias
    __half* hb    = (__half*)(ws + OFF_HB);
    __half* ipwb  = (__half*)(ws + OFF_WIP);
    __half* owwb  = (__half*)(ws + OFF_WOW);
    __half* l1wb  = (__half*)(ws + OFF_WL1);
    __half* l2wb  = (__half*)(ws + OFF_WL2);

    cudaFuncSetAttribute(gemm_fp16_kernel,
                         cudaFuncAttributeMaxDynamicSharedMemorySize, GSMEM);

    const size_t xbytes = (size_t)NTOK * CDIM * sizeof(float);
    const int gM = (NTOK + 127) / 128;   // 2049

    detect_mask_kernel<<<1, 256>>>((const unsigned int*)masks,
                                   (2 * 2 * NSETS * SETSZ) / 4);
    wconv_kernel<<<(4 * 768 * 256 + 255) / 256, 256>>>(ipw, ipwb, 4 * 768 * 256);
    wconv_kernel<<<(4 * 256 * 256 + 255) / 256, 256>>>(oww, owwb, 4 * 256 * 256);
    wconv_kernel<<<(4 * 1024 * 256 + 255) / 256, 256>>>(l1w, l1wb, 4 * 1024 * 256);
    wconv_kernel<<<(4 * 256 * 1024 + 255) / 256, 256>>>(l2w, l2wb, 4 * 256 * 1024);

    cudaMemcpyAsync(x, src, xbytes, cudaMemcpyDeviceToDevice);

    for (int blk = 0; blk < 2; blk++) {
        cudaMemcpyAsync(res, x, xbytes, cudaMemcpyDeviceToDevice);
        for (int i = 0; i < 2; i++) {
            int lid = blk * 2 + i;
            const int* ip = inds + (size_t)lid * NSETS * SETSZ;
            int moff = lid * NSETS * SETSZ;
            const float* pp = pos + (size_t)lid * NTOK * CDIM;

            gather_kernel<<<(NTOK * 64 + 255) / 256, 256>>>(
                x, pp, ip, qkb, featb);

            // in-proj QK (N=512) and V (N=256)
            gemm_fp16_kernel<<<dim3(2, gM), 512, GSMEM>>>(
                qkb, 256, ipwb + (size_t)lid * 768 * 256,
                ipb + (size_t)lid * 768, qkph, NTOK, 512, 0);
            gemm_fp16_kernel<<<dim3(1, gM), 512, GSMEM>>>(
                featb, 256, ipwb + (size_t)lid * 768 * 256 + (size_t)512 * 256,
                ipb + (size_t)lid * 768 + 512, vh, NTOK, 256, 0);

            attn_kernel<<<dim3(NSETS, 2), 144>>>(qkph, vh, masks, moff, attnb);

            gemm_fp16_kernel<<<dim3(1, gM), 512, GSMEM>>>(
                attnb, 256, owwb + (size_t)lid * 256 * 256,
                owb + (size_t)lid * 256, oh, NTOK, 256, 0);

            ln1_scatter_kernel<<<(NTOK + 7) / 8, 256>>>(
                x, oh, ip, n1g + (size_t)lid * 256, n1b + (size_t)lid * 256,
                x1, x1b);

            gemm_fp16_kernel<<<dim3(4, gM), 512, GSMEM>>>(
                x1b, 256, l1wb + (size_t)lid * 1024 * 256,
                l1b + (size_t)lid * 1024, hb, NTOK, 1024, 1);
            gemm_fp16_kernel<<<dim3(1, gM), 512, GSMEM>>>(
                hb, 1024, l2wb + (size_t)lid * 256 * 1024,
                l2b + (size_t)lid * 256, ffh, NTOK, 256, 0);

            ln2_enc_kernel<<<(NTOK + 7) / 8, 256>>>(
                x1, ffh, x,
                n2g + (size_t)lid * 256, n2b + (size_t)lid * 256,
                encg + (size_t)lid * 256, encb + (size_t)lid * 256);
        }
        float* dst = (blk == 1) ? outp : x;
        ln_res_kernel<<<(NTOK + 7) / 8, 256>>>(
            x, res, resg + (size_t)blk * 256, resb + (size_t)blk * 256, dst);
    }
}

// round 11
// speedup vs baseline: 1.0527x; 1.0527x over previous
#include <cuda_runtime.h>
#include <cuda_fp16.h>
#include <mma.h>
#include <cstdint>
#include <cmath>

using namespace nvcuda;

#define NTOK   262152
#define CDIM   256
#define NSETS  7282
#define SETSZ  36
#define NHEAD  8
#define DHEAD  32
#define DFFN   1024

// ---------------------------------------------------------------------------
// Workspace (single symbol, < 4GB). ~2.0 GB.
// Aliases (stream-order safe):
//   x1 (fp32) aliases qkph (fp16 512/tok; both NTOK*1024 bytes)
//   vh == oh == ffh (fp16, each dead before next writer)
//   x1b == qkb, attnb == featb
// ---------------------------------------------------------------------------
#define SZ_C   ((size_t)NTOK * 256 * 4)     // 268MB (fp32 256/tok)
#define SZ_H   ((size_t)NTOK * 256 * 2)     // 134MB (fp16 256/tok)
#define OFF_X    ((size_t)0)
#define OFF_RES  (OFF_X    + SZ_C)
#define OFF_QKPH (OFF_RES  + SZ_C)          // fp16 NTOK x 512; x1 fp32 aliases
#define OFF_VOF  (OFF_QKPH + SZ_C)          // fp16 vh / oh / ffh
#define OFF_QKB  (OFF_VOF  + SZ_H)          // fp16 (x1b aliases)
#define OFF_FEB  (OFF_QKB  + SZ_H)          // fp16 (attnb aliases)
#define OFF_HB   (OFF_FEB  + SZ_H)          // fp16 NTOK x 1024
#define OFF_WIP  (OFF_HB   + (size_t)NTOK * 1024 * 2)
#define OFF_WOW  (OFF_WIP + (size_t)4*768*256*2)
#define OFF_WL1  (OFF_WOW + (size_t)4*256*256*2)
#define OFF_WL2  (OFF_WL1 + (size_t)4*1024*256*2)
#define WS_TOT   (OFF_WL2 + (size_t)4*256*1024*2)

__device__ __align__(256) char g_ws[WS_TOT];
__device__ int g_mask_mode;

// ---------------------------------------------------------------------------
// Helpers
// ---------------------------------------------------------------------------
__device__ __forceinline__ uint32_t smem_u32(const void* p) {
    uint32_t a;
    asm("{ .reg .u64 t; cvta.to.shared.u64 t, %1; cvt.u32.u64 %0, t; }"
        : "=r"(a) : "l"(p));
    return a;
}
__device__ __forceinline__ void cp16(uint32_t dst, const void* src, int sz) {
    asm volatile("cp.async.cg.shared.global [%0], [%1], 16, %2;"
                 :: "r"(dst), "l"(src), "r"(sz) : "memory");
}
#define CP_COMMIT() asm volatile("cp.async.commit_group;" ::: "memory")
#define CP_WAIT1()  asm volatile("cp.async.wait_group 1;" ::: "memory")
#define CP_WAIT0()  asm volatile("cp.async.wait_group 0;" ::: "memory")

__device__ __forceinline__ uint32_t pack2h(float a, float b) {
    __half2 h;
    h.x = __float2half_rn(a); h.y = __float2half_rn(b);
    return *reinterpret_cast<uint32_t*>(&h);
}
__device__ __forceinline__ void write4h(__half* p, float4 v) {
    *(uint2*)p = make_uint2(pack2h(v.x, v.y), pack2h(v.z, v.w));
}
__device__ __forceinline__ float4 read4h(const __half* p) {
    const __half2* h = (const __half2*)p;
    float2 a = __half22float2(h[0]);
    float2 b = __half22float2(h[1]);
    return make_float4(a.x, a.y, b.x, b.y);
}

// ---------------------------------------------------------------------------
// Weight converter: fp32 -> plain fp16
// ---------------------------------------------------------------------------
__global__ __launch_bounds__(256) void wconv_kernel(
    const float* __restrict__ src, __half* __restrict__ dst, int n)
{
    int idx = blockIdx.x * 256 + threadIdx.x;
    if (idx >= n) return;
    dst[idx] = __float2half_rn(src[idx]);
}

// ---------------------------------------------------------------------------
// Mask dtype detector
// ---------------------------------------------------------------------------
__global__ void detect_mask_kernel(const unsigned int* __restrict__ w, int nwords)
{
    __shared__ int f32f, u8f;
    if (threadIdx.x == 0) { f32f = 0; u8f = 0; }
    __syncthreads();
    int lf = 0, lu = 0;
    for (int i = threadIdx.x; i < nwords; i += blockDim.x) {
        unsigned int x = w[i];
        if (x == 0x3F800000u) lf = 1;
        else if (x > 1u)      lu = 1;
    }
    if (lf) f32f = 1;
    if (lu) u8f = 1;
    __syncthreads();
    if (threadIdx.x == 0) g_mask_mode = f32f ? 2 : (u8f ? 1 : 0);
}

// ---------------------------------------------------------------------------
// Gather: fp16 qk (= x[inds]+pos[inds]) and feat (= x[inds])
// ---------------------------------------------------------------------------
__global__ __launch_bounds__(256) void gather_kernel(
    const float* __restrict__ x, const float* __restrict__ pos,
    const int* __restrict__ inds, __half* __restrict__ qkb,
    __half* __restrict__ featb)
{
    int idx = blockIdx.x * 256 + threadIdx.x;
    if (idx >= NTOK * 64) return;
    int j  = idx >> 6;
    int c4 = idx & 63;
    int t  = inds[j];
    float4 xv = ((const float4*)x)  [(size_t)t * 64 + c4];
    float4 pv = ((const float4*)pos)[(size_t)t * 64 + c4];
    float4 q  = make_float4(xv.x + pv.x, xv.y + pv.y, xv.z + pv.z, xv.w + pv.w);
    write4h(featb + (size_t)j * 256 + c4 * 4, xv);
    write4h(qkb   + (size_t)j * 256 + c4 * 4, q);
}

// ---------------------------------------------------------------------------
// fp16 GEMM: C[m,n] = A[m,:] . W[n,:] + bias[n] (+GELU), fp32 acc, fp16 out.
// CTA 128x128, BK=64, 3-stage cp.async, 8 warps (4x2) of 32x64, 2 CTAs/SM.
// ---------------------------------------------------------------------------
#define STAGE_B 36864          // A 128x144B + W 128x144B
#define GSMEM   (3 * STAGE_B)  // 110592; epilogue scratch aliases stage 0

__global__ __launch_bounds__(256, 2) void gemm_fp16_kernel(
    const __half* __restrict__ A, int KA,
    const __half* __restrict__ W, const float* __restrict__ bias,
    __half* __restrict__ C, int M, int N, int act)
{
    extern __shared__ char smem[];
    const uint32_t sb = smem_u32(smem);
    const int tid  = threadIdx.x;
    const int wid  = tid >> 5;
    const int lane = tid & 31;
    const int wr   = wid >> 1;   // 0..3
    const int wc   = wid & 1;    // 0..1
    const int m0   = blockIdx.y * 128;
    const int n0   = blockIdx.x * 128;
    const int NC   = KA >> 6;

    wmma::fragment<wmma::accumulator, 16, 16, 16, float> acc[2][4];
#pragma unroll
    for (int i = 0; i < 2; i++)
#pragma unroll
        for (int j = 0; j < 4; j++) wmma::fill_fragment(acc[i][j], 0.0f);

    // Fill one stage: 128 rows x 128B for A and W (8 x 16B chunks per row).
    auto load_stage = [&](int slot, int c) {
        const int k0 = c << 6;
        const uint32_t base = sb + slot * STAGE_B;
#pragma unroll
        for (int it = 0; it < 4; it++) {
            int i  = tid + it * 256;      // 0..1023
            int r  = i >> 3;              // row 0..127
            int ch = i & 7;               // 16B chunk 0..7
            int gr = m0 + r;
            const __half* sa =
                A + (size_t)(gr < M ? gr : M - 1) * KA + k0 + ch * 8;
            cp16(base + r * 144 + ch * 16, sa, gr < M ? 16 : 0);
            const __half* sw = W + (size_t)(n0 + r) * KA + k0 + ch * 8;
            cp16(base + 18432 + r * 144 + ch * 16, sw, 16);
        }
    };

    load_stage(0, 0); CP_COMMIT();
    load_stage(1, 1); CP_COMMIT();

    for (int c = 0; c < NC; c++) {
        CP_WAIT1();
        __syncthreads();
        const int slot = c % 3;
        const __half* sA = (const __half*)(smem + slot * STAGE_B);
        const __half* sB = (const __half*)(smem + slot * STAGE_B + 18432);
#pragma unroll
        for (int kk = 0; kk < 4; kk++) {
            wmma::fragment<wmma::matrix_a, 16, 16, 16, __half,
                           wmma::row_major> a[2];
            wmma::fragment<wmma::matrix_b, 16, 16, 16, __half,
                           wmma::col_major> b[4];
#pragma unroll
            for (int i = 0; i < 2; i++)
                wmma::load_matrix_sync(a[i], sA + (wr * 32 + i * 16) * 72 + kk * 16, 72);
#pragma unroll
            for (int j = 0; j < 4; j++)
                wmma::load_matrix_sync(b[j], sB + (wc * 64 + j * 16) * 72 + kk * 16, 72);
#pragma unroll
            for (int i = 0; i < 2; i++)
#pragma unroll
                for (int j = 0; j < 4; j++)
                    wmma::mma_sync(acc[i][j], a[i], b[j], acc[i][j]);
        }
        __syncthreads();
        const int cn = c + 2;
        if (cn < NC) load_stage(cn % 3, cn);
        CP_COMMIT();
    }

    CP_WAIT0();
    __syncthreads();

    // epilogue: scratch aliases stage smem (mainloop done)
    float* scr = (float*)smem + wid * 16 * 24;
#pragma unroll
    for (int i = 0; i < 2; i++)
#pragma unroll
        for (int j = 0; j < 4; j++) {
            wmma::store_matrix_sync(scr, acc[i][j], 24, wmma::mem_row_major);
            __syncwarp();
            int r  = lane >> 1;
            int ch = (lane & 1) * 8;
            int gr = m0 + wr * 32 + i * 16 + r;
            int gc = n0 + wc * 64 + j * 16 + ch;
            if (gr < M) {
                float4 b0 = *(const float4*)(bias + gc);
                float4 b1 = *(const float4*)(bias + gc + 4);
                float v[8];
                v[0] = scr[r * 24 + ch + 0] + b0.x;
                v[1] = scr[r * 24 + ch + 1] + b0.y;
                v[2] = scr[r * 24 + ch + 2] + b0.z;
                v[3] = scr[r * 24 + ch + 3] + b0.w;
                v[4] = scr[r * 24 + ch + 4] + b1.x;
                v[5] = scr[r * 24 + ch + 5] + b1.y;
                v[6] = scr[r * 24 + ch + 6] + b1.z;
                v[7] = scr[r * 24 + ch + 7] + b1.w;
                if (act) {
#pragma unroll
                    for (int e = 0; e < 8; e++)
                        v[e] = 0.5f * v[e] *
                               (1.0f + erff(v[e] * 0.70710678118654752f));
                }
                __half* hp = C + (size_t)gr * N + gc;
                write4h(hp,     make_float4(v[0], v[1], v[2], v[3]));
                write4h(hp + 4, make_float4(v[4], v[5], v[6], v[7]));
            }
            __syncwarp();
        }
}

// ---------------------------------------------------------------------------
// Set attention (fp32 math, fp16 in/out)
// ---------------------------------------------------------------------------
__global__ __launch_bounds__(144, 1) void attn_kernel(
    const __half* __restrict__ qkp, const __half* __restrict__ vb,
    const void* __restrict__ maskp, int mask_off,
    __half* __restrict__ outb)
{
    const int s   = blockIdx.x;
    const int h0  = blockIdx.y * 4;
    const int tid = threadIdx.x;
    const int hl  = tid / SETSZ;
    const int l   = tid - hl * SETSZ;

    __shared__ float ks[4][SETSZ][DHEAD];
    __shared__ float vs[4][SETSZ][DHEAD];
    __shared__ float msk[SETSZ];

    if (tid < SETSZ) {
        int gi = mask_off + s * SETSZ + tid;
        int mode = g_mask_mode;
        bool m;
        if (mode == 0)      m = ((const int*)maskp)[gi] != 0;
        else if (mode == 1) m = ((const unsigned char*)maskp)[gi] != 0;
        else                m = ((const float*)maskp)[gi] != 0.0f;
        msk[tid] = m ? -INFINITY : 0.0f;
    }
    for (int idx = tid; idx < 4 * SETSZ * DHEAD; idx += 144) {
        int d  = idx & (DHEAD - 1);
        int m  = (idx >> 5) % SETSZ;
        int hh = idx / (DHEAD * SETSZ);
        size_t row = (size_t)s * SETSZ + m;
        ks[hh][m][d] = __half2float(qkp[row * 512 + 256 + (size_t)(h0 + hh) * DHEAD + d]);
        vs[hh][m][d] = __half2float(vb [row * 256 +       (size_t)(h0 + hh) * DHEAD + d]);
    }
    __syncthreads();

    float q[DHEAD];
    {
        const __half2* qr = (const __half2*)(qkp + ((size_t)s * SETSZ + l) * 512
                                             + (size_t)(h0 + hl) * DHEAD);
#pragma unroll
        for (int p = 0; p < 16; p++) {
            float2 f = __half22float2(qr[p]);
            q[2 * p] = f.x; q[2 * p + 1] = f.y;
        }
    }
    const float scale = 0.17677669529663687f;
    float sc[SETSZ];
    float mx = -INFINITY;
#pragma unroll
    for (int m = 0; m < SETSZ; m++) {
        float a = 0.f;
#pragma unroll
        for (int d = 0; d < DHEAD; d++) a += q[d] * ks[hl][m][d];
        a = a * scale + msk[m];
        sc[m] = a;
        mx = fmaxf(mx, a);
    }
    float den = 0.f;
#pragma unroll
    for (int m = 0; m < SETSZ; m++) { float e = expf(sc[m] - mx); sc[m] = e; den += e; }
    float inv = 1.0f / den;
    float o[DHEAD];
#pragma unroll
    for (int d = 0; d < DHEAD; d++) o[d] = 0.f;
#pragma unroll
    for (int m = 0; m < SETSZ; m++) {
        float a = sc[m] * inv;
#pragma unroll
        for (int d = 0; d < DHEAD; d++) o[d] += a * vs[hl][m][d];
    }
    __half* op = outb + ((size_t)s * SETSZ + l) * 256 + (size_t)(h0 + hl) * DHEAD;
#pragma unroll
    for (int p = 0; p < 8; p++)
        write4h(op + p * 4,
                make_float4(o[p*4], o[p*4+1], o[p*4+2], o[p*4+3]));
}

// ---------------------------------------------------------------------------
// LayerNorm helpers
// ---------------------------------------------------------------------------
__device__ __forceinline__ float wsum(float v)
{
#pragma unroll
    for (int o = 16; o > 0; o >>= 1) v += __shfl_xor_sync(0xffffffffu, v, o);
    return v;
}

__device__ __forceinline__ void ln8(float4& v0, float4& v1,
                                    const float* __restrict__ g,
                                    const float* __restrict__ b, int lane)
{
    float s  = v0.x + v0.y + v0.z + v0.w + v1.x + v1.y + v1.z + v1.w;
    float ss = v0.x*v0.x + v0.y*v0.y + v0.z*v0.z + v0.w*v0.w
             + v1.x*v1.x + v1.y*v1.y + v1.z*v1.z + v1.w*v1.w;
    s = wsum(s); ss = wsum(ss);
    float mean = s * (1.0f / 256.0f);
    float var  = ss * (1.0f / 256.0f) - mean * mean;
    float inv  = rsqrtf(fmaxf(var, 0.0f) + 1e-5f);
    float4 G0 = ((const float4*)g)[lane];
    float4 G1 = ((const float4*)g)[lane + 32];
    float4 B0 = ((const float4*)b)[lane];
    float4 B1 = ((const float4*)b)[lane + 32];
    v0.x = (v0.x - mean) * inv * G0.x + B0.x;
    v0.y = (v0.y - mean) * inv * G0.y + B0.y;
    v0.z = (v0.z - mean) * inv * G0.z + B0.z;
    v0.w = (v0.w - mean) * inv * G0.w + B0.w;
    v1.x = (v1.x - mean) * inv * G1.x + B1.x;
    v1.y = (v1.y - mean) * inv * G1.y + B1.y;
    v1.z = (v1.z - mean) * inv * G1.z + B1.z;
    v1.w = (v1.w - mean) * inv * G1.w + B1.w;
}

__device__ __forceinline__ float4 f4add(float4 a, float4 b)
{ return make_float4(a.x + b.x, a.y + b.y, a.z + b.z, a.w + b.w); }

// x1[t] = LN(x[t] + o[j]), t = inds[j]; o fp16; fp32 + fp16 outputs
__global__ __launch_bounds__(256) void ln1_scatter_kernel(
    const float* __restrict__ x, const __half* __restrict__ o,
    const int* __restrict__ inds, const float* __restrict__ g,
    const float* __restrict__ b, float* __restrict__ out,
    __half* __restrict__ outb)
{
    int w = (blockIdx.x << 3) + (threadIdx.x >> 5);
    if (w >= NTOK) return;
    int lane = threadIdx.x & 31;
    int t = inds[w];
    const float4* xr = (const float4*)(x + (size_t)t * 256);
    const __half* orr = o + (size_t)w * 256;
    float4 v0 = f4add(xr[lane],      read4h(orr + lane * 4));
    float4 v1 = f4add(xr[lane + 32], read4h(orr + 128 + lane * 4));
    ln8(v0, v1, g, b, lane);
    ((float4*)(out + (size_t)t * 256))[lane]      = v0;
    ((float4*)(out + (size_t)t * 256))[lane + 32] = v1;
    __half* ar = outb + (size_t)t * 256;
    write4h(ar + lane * 4,       v0);
    write4h(ar + 128 + lane * 4, v1);
}

// xio[t] = LN_enc( LN_2(x1 + ff) + xio ); ff fp16
__global__ __launch_bounds__(256) void ln2_enc_kernel(
    const float* __restrict__ x1, const __half* __restrict__ ff,
    float* __restrict__ xio,
    const float* __restrict__ g2, const float* __restrict__ b2,
    const float* __restrict__ ge, const float* __restrict__ be)
{
    int w = (blockIdx.x << 3) + (threadIdx.x >> 5);
    if (w >= NTOK) return;
    int lane = threadIdx.x & 31;
    const float4* r1 = (const float4*)(x1 + (size_t)w * 256);
    const __half* rf = ff + (size_t)w * 256;
    float4* rx = (float4*)(xio + (size_t)w * 256);
    float4 v0 = f4add(r1[lane],      read4h(rf + lane * 4));
    float4 v1 = f4add(r1[lane + 32], read4h(rf + 128 + lane * 4));
    ln8(v0, v1, g2, b2, lane);
    v0 = f4add(v0, rx[lane]);
    v1 = f4add(v1, rx[lane + 32]);
    ln8(v0, v1, ge, be, lane);
    rx[lane]      = v0;
    rx[lane + 32] = v1;
}

__global__ __launch_bounds__(256) void ln_res_kernel(
    const float* __restrict__ x, const float* __restrict__ r,
    const float* __restrict__ g, const float* __restrict__ b,
    float* __restrict__ out)
{
    int w = (blockIdx.x << 3) + (threadIdx.x >> 5);
    if (w >= NTOK) return;
    int lane = threadIdx.x & 31;
    const float4* xr = (const float4*)(x + (size_t)w * 256);
    const float4* rr = (const float4*)(r + (size_t)w * 256);
    float4 v0 = f4add(xr[lane],      rr[lane]);
    float4 v1 = f4add(xr[lane + 32], rr[lane + 32]);
    ln8(v0, v1, g, b, lane);
    ((float4*)(out + (size_t)w * 256))[lane]      = v0;
    ((float4*)(out + (size_t)w * 256))[lane + 32] = v1;
}

// ---------------------------------------------------------------------------
// Orchestration
// ---------------------------------------------------------------------------
extern "C" void kernel_launch(void* const* d_in, const int* in_sizes, int n_in,
                              void* d_out, int out_size)
{
    const float* src   = (const float*)d_in[0];
    const float* pos   = (const float*)d_in[1];
    const int*   inds  = (const int*)  d_in[2];
    const void*  masks =               d_in[3];
    const float* ipw   = (const float*)d_in[4];
    const float* ipb   = (const float*)d_in[5];
    const float* oww   = (const float*)d_in[6];
    const float* owb   = (const float*)d_in[7];
    const float* l1w   = (const float*)d_in[8];
    const float* l1b   = (const float*)d_in[9];
    const float* l2w   = (const float*)d_in[10];
    const float* l2b   = (const float*)d_in[11];
    const float* n1g   = (const float*)d_in[12];
    const float* n1b   = (const float*)d_in[13];
    const float* n2g   = (const float*)d_in[14];
    const float* n2b   = (const float*)d_in[15];
    const float* encg  = (const float*)d_in[16];
    const float* encb  = (const float*)d_in[17];
    const float* resg  = (const float*)d_in[18];
    const float* resb  = (const float*)d_in[19];
    float* outp = (float*)d_out;

    char* ws;
    cudaGetSymbolAddress((void**)&ws, g_ws);
    float*  x     = (float*)(ws + OFF_X);
    float*  res   = (float*)(ws + OFF_RES);
    __half* qkph  = (__half*)(ws + OFF_QKPH);
    float*  x1    = (float*)(ws + OFF_QKPH);   // alias: qkph dead after attn
    __half* vh    = (__half*)(ws + OFF_VOF);
    __half* oh    = (__half*)(ws + OFF_VOF);   // alias
    __half* ffh   = (__half*)(ws + OFF_VOF);   // alias
    __half* qkb   = (__half*)(ws + OFF_QKB);
    __half* x1b   = (__half*)(ws + OFF_QKB);   // alias
    __half* featb = (__half*)(ws + OFF_FEB);
    __half* attnb = (__half*)(ws + OFF_FEB);   // alias
    __half* hb    = (__half*)(ws + OFF_HB);
    __half* ipwb  = (__half*)(ws + OFF_WIP);
    __half* owwb  = (__half*)(ws + OFF_WOW);
    __half* l1wb  = (__half*)(ws + OFF_WL1);
    __half* l2wb  = (__half*)(ws + OFF_WL2);

    cudaFuncSetAttribute(gemm_fp16_kernel,
                         cudaFuncAttributeMaxDynamicSharedMemorySize, GSMEM);

    const size_t xbytes = (size_t)NTOK * CDIM * sizeof(float);
    const int gM = (NTOK + 127) / 128;   // 2049

    detect_mask_kernel<<<1, 256>>>((const unsigned int*)masks,
                                   (2 * 2 * NSETS * SETSZ) / 4);
    wconv_kernel<<<(4 * 768 * 256 + 255) / 256, 256>>>(ipw, ipwb, 4 * 768 * 256);
    wconv_kernel<<<(4 * 256 * 256 + 255) / 256, 256>>>(oww, owwb, 4 * 256 * 256);
    wconv_kernel<<<(4 * 1024 * 256 + 255) / 256, 256>>>(l1w, l1wb, 4 * 1024 * 256);
    wconv_kernel<<<(4 * 256 * 1024 + 255) / 256, 256>>>(l2w, l2wb, 4 * 256 * 1024);

    cudaMemcpyAsync(x, src, xbytes, cudaMemcpyDeviceToDevice);

    for (int blk = 0; blk < 2; blk++) {
        cudaMemcpyAsync(res, x, xbytes, cudaMemcpyDeviceToDevice);
        for (int i = 0; i < 2; i++) {
            int lid = blk * 2 + i;
            const int* ip = inds + (size_t)lid * NSETS * SETSZ;
            int moff = lid * NSETS * SETSZ;
            const float* pp = pos + (size_t)lid * NTOK * CDIM;

            gather_kernel<<<(NTOK * 64 + 255) / 256, 256>>>(
                x, pp, ip, qkb, featb);

            // in-proj QK (N=512) and V (N=256)
            gemm_fp16_kernel<<<dim3(4, gM), 256, GSMEM>>>(
                qkb, 256, ipwb + (size_t)lid * 768 * 256,
                ipb + (size_t)lid * 768, qkph, NTOK, 512, 0);
            gemm_fp16_kernel<<<dim3(2, gM), 256, GSMEM>>>(
                featb, 256, ipwb + (size_t)lid * 768 * 256 + (size_t)512 * 256,
                ipb + (size_t)lid * 768 + 512, vh, NTOK, 256, 0);

            attn_kernel<<<dim3(NSETS, 2), 144>>>(qkph, vh, masks, moff, attnb);

            gemm_fp16_kernel<<<dim3(2, gM), 256, GSMEM>>>(
                attnb, 256, owwb + (size_t)lid * 256 * 256,
                owb + (size_t)lid * 256, oh, NTOK, 256, 0);

            ln1_scatter_kernel<<<(NTOK + 7) / 8, 256>>>(
                x, oh, ip, n1g + (size_t)lid * 256, n1b + (size_t)lid * 256,
                x1, x1b);

            gemm_fp16_kernel<<<dim3(8, gM), 256, GSMEM>>>(
                x1b, 256, l1wb + (size_t)lid * 1024 * 256,
                l1b + (size_t)lid * 1024, hb, NTOK, 1024, 1);
            gemm_fp16_kernel<<<dim3(2, gM), 256, GSMEM>>>(
                hb, 1024, l2wb + (size_t)lid * 256 * 1024,
                l2b + (size_t)lid * 256, ffh, NTOK, 256, 0);

            ln2_enc_kernel<<<(NTOK + 7) / 8, 256>>>(
                x1, ffh, x,
                n2g + (size_t)lid * 256, n2b + (size_t)lid * 256,
                encg + (size_t)lid * 256, encb + (size_t)lid * 256);
        }
        float* dst = (blk == 1) ? outp : x;
        ln_res_kernel<<<(NTOK + 7) / 8, 256>>>(
            x, res, resg + (size_t)blk * 256, resb + (size_t)blk * 256, dst);
    }
}

// round 12
// speedup vs baseline: 1.0808x; 1.0267x over previous
#include <cuda_runtime.h>
#include <cuda_fp16.h>
#include <mma.h>
#include <cstdint>
#include <cmath>

using namespace nvcuda;

#define NTOK   262152
#define CDIM   256
#define NSETS  7282
#define SETSZ  36
#define NHEAD  8
#define DHEAD  32
#define DFFN   1024

// ---------------------------------------------------------------------------
// Workspace (single symbol, < 4GB). ~2.0 GB.
// Aliases (stream-order safe):
//   x1 (fp32) aliases qkph (fp16 512/tok; both NTOK*1024 bytes)
//   vh == oh == ffh (fp16, each dead before next writer)
//   x1b == qkb, attnb == featb
// ---------------------------------------------------------------------------
#define SZ_C   ((size_t)NTOK * 256 * 4)     // 268MB (fp32 256/tok)
#define SZ_H   ((size_t)NTOK * 256 * 2)     // 134MB (fp16 256/tok)
#define OFF_X    ((size_t)0)
#define OFF_RES  (OFF_X    + SZ_C)
#define OFF_QKPH (OFF_RES  + SZ_C)          // fp16 NTOK x 512; x1 fp32 aliases
#define OFF_VOF  (OFF_QKPH + SZ_C)          // fp16 vh / oh / ffh
#define OFF_QKB  (OFF_VOF  + SZ_H)          // fp16 (x1b aliases)
#define OFF_FEB  (OFF_QKB  + SZ_H)          // fp16 (attnb aliases)
#define OFF_HB   (OFF_FEB  + SZ_H)          // fp16 NTOK x 1024
#define OFF_WIP  (OFF_HB   + (size_t)NTOK * 1024 * 2)
#define OFF_WOW  (OFF_WIP + (size_t)4*768*256*2)
#define OFF_WL1  (OFF_WOW + (size_t)4*256*256*2)
#define OFF_WL2  (OFF_WL1 + (size_t)4*1024*256*2)
#define WS_TOT   (OFF_WL2 + (size_t)4*256*1024*2)

__device__ __align__(256) char g_ws[WS_TOT];
__device__ int g_mask_mode;

// ---------------------------------------------------------------------------
// Helpers
// ---------------------------------------------------------------------------
__device__ __forceinline__ uint32_t smem_u32(const void* p) {
    uint32_t a;
    asm("{ .reg .u64 t; cvta.to.shared.u64 t, %1; cvt.u32.u64 %0, t; }"
        : "=r"(a) : "l"(p));
    return a;
}
__device__ __forceinline__ void cp16(uint32_t dst, const void* src, int sz) {
    asm volatile("cp.async.cg.shared.global [%0], [%1], 16, %2;"
                 :: "r"(dst), "l"(src), "r"(sz) : "memory");
}
#define CP_COMMIT() asm volatile("cp.async.commit_group;" ::: "memory")
#define CP_WAIT1()  asm volatile("cp.async.wait_group 1;" ::: "memory")
#define CP_WAIT0()  asm volatile("cp.async.wait_group 0;" ::: "memory")

__device__ __forceinline__ uint32_t pack2h(float a, float b) {
    __half2 h;
    h.x = __float2half_rn(a); h.y = __float2half_rn(b);
    return *reinterpret_cast<uint32_t*>(&h);
}
__device__ __forceinline__ void write4h(__half* p, float4 v) {
    *(uint2*)p = make_uint2(pack2h(v.x, v.y), pack2h(v.z, v.w));
}
__device__ __forceinline__ float4 read4h(const __half* p) {
    const __half2* h = (const __half2*)p;
    float2 a = __half22float2(h[0]);
    float2 b = __half22float2(h[1]);
    return make_float4(a.x, a.y, b.x, b.y);
}

// ---------------------------------------------------------------------------
// Weight converter: fp32 -> plain fp16
// ---------------------------------------------------------------------------
__global__ __launch_bounds__(256) void wconv_kernel(
    const float* __restrict__ src, __half* __restrict__ dst, int n)
{
    int idx = blockIdx.x * 256 + threadIdx.x;
    if (idx >= n) return;
    dst[idx] = __float2half_rn(src[idx]);
}

// ---------------------------------------------------------------------------
// Mask dtype detector
// ---------------------------------------------------------------------------
__global__ void detect_mask_kernel(const unsigned int* __restrict__ w, int nwords)
{
    __shared__ int f32f, u8f;
    if (threadIdx.x == 0) { f32f = 0; u8f = 0; }
    __syncthreads();
    int lf = 0, lu = 0;
    for (int i = threadIdx.x; i < nwords; i += blockDim.x) {
        unsigned int x = w[i];
        if (x == 0x3F800000u) lf = 1;
        else if (x > 1u)      lu = 1;
    }
    if (lf) f32f = 1;
    if (lu) u8f = 1;
    __syncthreads();
    if (threadIdx.x == 0) g_mask_mode = f32f ? 2 : (u8f ? 1 : 0);
}

// ---------------------------------------------------------------------------
// Gather: fp16 qk (= x[inds]+pos[inds]) and feat (= x[inds])
// ---------------------------------------------------------------------------
__global__ __launch_bounds__(256) void gather_kernel(
    const float* __restrict__ x, const float* __restrict__ pos,
    const int* __restrict__ inds, __half* __restrict__ qkb,
    __half* __restrict__ featb)
{
    int idx = blockIdx.x * 256 + threadIdx.x;
    if (idx >= NTOK * 64) return;
    int j  = idx >> 6;
    int c4 = idx & 63;
    int t  = inds[j];
    float4 xv = ((const float4*)x)  [(size_t)t * 64 + c4];
    float4 pv = ((const float4*)pos)[(size_t)t * 64 + c4];
    float4 q  = make_float4(xv.x + pv.x, xv.y + pv.y, xv.z + pv.z, xv.w + pv.w);
    write4h(featb + (size_t)j * 256 + c4 * 4, xv);
    write4h(qkb   + (size_t)j * 256 + c4 * 4, q);
}

// ---------------------------------------------------------------------------
// fp16 GEMM: C[m,n] = A[m,:] . W[n,:] + bias[n] (+GELU), fp32 acc, fp16 out.
// CTA 128x128, BK=64, 3-stage cp.async, 8 warps (4x2) of 32x64, 2 CTAs/SM.
// One __syncthreads per mainloop iteration; whole-tile staged epilogue.
// ---------------------------------------------------------------------------
#define STAGE_B 36864          // A 128x144B + W 128x144B
#define GSMEM   (3 * STAGE_B)  // 110592; epilogue scratch aliases stages

__global__ __launch_bounds__(256, 2) void gemm_fp16_kernel(
    const __half* __restrict__ A, int KA,
    const __half* __restrict__ W, const float* __restrict__ bias,
    __half* __restrict__ C, int M, int N, int act)
{
    extern __shared__ char smem[];
    const uint32_t sb = smem_u32(smem);
    const int tid  = threadIdx.x;
    const int wid  = tid >> 5;
    const int lane = tid & 31;
    const int wr   = wid >> 1;   // 0..3
    const int wc   = wid & 1;    // 0..1
    const int m0   = blockIdx.y * 128;
    const int n0   = blockIdx.x * 128;
    const int NC   = KA >> 6;

    wmma::fragment<wmma::accumulator, 16, 16, 16, float> acc[2][4];
#pragma unroll
    for (int i = 0; i < 2; i++)
#pragma unroll
        for (int j = 0; j < 4; j++) wmma::fill_fragment(acc[i][j], 0.0f);

    auto load_stage = [&](int slot, int c) {
        const int k0 = c << 6;
        const uint32_t base = sb + slot * STAGE_B;
#pragma unroll
        for (int it = 0; it < 4; it++) {
            int i  = tid + it * 256;      // 0..1023
            int r  = i >> 3;              // row 0..127
            int ch = i & 7;               // 16B chunk 0..7
            int gr = m0 + r;
            const __half* sa =
                A + (size_t)(gr < M ? gr : M - 1) * KA + k0 + ch * 8;
            cp16(base + r * 144 + ch * 16, sa, gr < M ? 16 : 0);
            const __half* sw = W + (size_t)(n0 + r) * KA + k0 + ch * 8;
            cp16(base + 18432 + r * 144 + ch * 16, sw, 16);
        }
    };

    load_stage(0, 0); CP_COMMIT();
    load_stage(1, 1); CP_COMMIT();

    for (int c = 0; c < NC; c++) {
        CP_WAIT1();
        __syncthreads();
        const int slot = c % 3;
        const __half* sA = (const __half*)(smem + slot * STAGE_B);
        const __half* sB = (const __half*)(smem + slot * STAGE_B + 18432);
#pragma unroll
        for (int kk = 0; kk < 4; kk++) {
            wmma::fragment<wmma::matrix_a, 16, 16, 16, __half,
                           wmma::row_major> a[2];
            wmma::fragment<wmma::matrix_b, 16, 16, 16, __half,
                           wmma::col_major> b[4];
#pragma unroll
            for (int i = 0; i < 2; i++)
                wmma::load_matrix_sync(a[i], sA + (wr * 32 + i * 16) * 72 + kk * 16, 72);
#pragma unroll
            for (int j = 0; j < 4; j++)
                wmma::load_matrix_sync(b[j], sB + (wc * 64 + j * 16) * 72 + kk * 16, 72);
#pragma unroll
            for (int i = 0; i < 2; i++)
#pragma unroll
                for (int j = 0; j < 4; j++)
                    wmma::mma_sync(acc[i][j], a[i], b[j], acc[i][j]);
        }
        // safe without a second barrier: slot (c+2)%3 was last read in iter
        // c-1, and every warp passed this iteration's top barrier after that.
        const int cn = c + 2;
        if (cn < NC) load_stage(cn % 3, cn);
        CP_COMMIT();
    }

    CP_WAIT0();
    __syncthreads();

    // epilogue: each warp stages its full 32x64 fp32 tile once (stride 68,
    // conflict-free 16B phases), then each lane emits one row.
    float* scr = (float*)smem + wid * 32 * 68;
#pragma unroll
    for (int i = 0; i < 2; i++)
#pragma unroll
        for (int j = 0; j < 4; j++)
            wmma::store_matrix_sync(scr + i * 16 * 68 + j * 16, acc[i][j], 68,
                                    wmma::mem_row_major);
    __syncwarp();
    int gr = m0 + wr * 32 + lane;
    if (gr < M) {
        const float* row = scr + lane * 68;
        const float* bp  = bias + n0 + wc * 64;
        __half* hp = C + (size_t)gr * N + n0 + wc * 64;
#pragma unroll
        for (int p = 0; p < 4; p++) {
            float v[16];
#pragma unroll
            for (int q = 0; q < 4; q++) {
                float4 a4 = *(const float4*)(row + p * 16 + q * 4);
                float4 b4 = *(const float4*)(bp  + p * 16 + q * 4);
                v[q*4+0] = a4.x + b4.x;
                v[q*4+1] = a4.y + b4.y;
                v[q*4+2] = a4.z + b4.z;
                v[q*4+3] = a4.w + b4.w;
            }
            if (act) {
#pragma unroll
                for (int e = 0; e < 16; e++)
                    v[e] = 0.5f * v[e] *
                           (1.0f + erff(v[e] * 0.70710678118654752f));
            }
            uint4 o0, o1;
            o0.x = pack2h(v[0],  v[1]);  o0.y = pack2h(v[2],  v[3]);
            o0.z = pack2h(v[4],  v[5]);  o0.w = pack2h(v[6],  v[7]);
            o1.x = pack2h(v[8],  v[9]);  o1.y = pack2h(v[10], v[11]);
            o1.z = pack2h(v[12], v[13]); o1.w = pack2h(v[14], v[15]);
            *(uint4*)(hp + p * 16)     = o0;
            *(uint4*)(hp + p * 16 + 8) = o1;
        }
    }
}

// ---------------------------------------------------------------------------
// Set attention (fp32 math, fp16 in/out)
// ---------------------------------------------------------------------------
__global__ __launch_bounds__(144, 1) void attn_kernel(
    const __half* __restrict__ qkp, const __half* __restrict__ vb,
    const void* __restrict__ maskp, int mask_off,
    __half* __restrict__ outb)
{
    const int s   = blockIdx.x;
    const int h0  = blockIdx.y * 4;
    const int tid = threadIdx.x;
    const int hl  = tid / SETSZ;
    const int l   = tid - hl * SETSZ;

    __shared__ float ks[4][SETSZ][DHEAD];
    __shared__ float vs[4][SETSZ][DHEAD];
    __shared__ float msk[SETSZ];

    if (tid < SETSZ) {
        int gi = mask_off + s * SETSZ + tid;
        int mode = g_mask_mode;
        bool m;
        if (mode == 0)      m = ((const int*)maskp)[gi] != 0;
        else if (mode == 1) m = ((const unsigned char*)maskp)[gi] != 0;
        else                m = ((const float*)maskp)[gi] != 0.0f;
        msk[tid] = m ? -INFINITY : 0.0f;
    }
    for (int idx = tid; idx < 4 * SETSZ * DHEAD; idx += 144) {
        int d  = idx & (DHEAD - 1);
        int m  = (idx >> 5) % SETSZ;
        int hh = idx / (DHEAD * SETSZ);
        size_t row = (size_t)s * SETSZ + m;
        ks[hh][m][d] = __half2float(qkp[row * 512 + 256 + (size_t)(h0 + hh) * DHEAD + d]);
        vs[hh][m][d] = __half2float(vb [row * 256 +       (size_t)(h0 + hh) * DHEAD + d]);
    }
    __syncthreads();

    float q[DHEAD];
    {
        const __half2* qr = (const __half2*)(qkp + ((size_t)s * SETSZ + l) * 512
                                             + (size_t)(h0 + hl) * DHEAD);
#pragma unroll
        for (int p = 0; p < 16; p++) {
            float2 f = __half22float2(qr[p]);
            q[2 * p] = f.x; q[2 * p + 1] = f.y;
        }
    }
    const float scale = 0.17677669529663687f;
    float sc[SETSZ];
    float mx = -INFINITY;
#pragma unroll
    for (int m = 0; m < SETSZ; m++) {
        float a = 0.f;
#pragma unroll
        for (int d = 0; d < DHEAD; d++) a += q[d] * ks[hl][m][d];
        a = a * scale + msk[m];
        sc[m] = a;
        mx = fmaxf(mx, a);
    }
    float den = 0.f;
#pragma unroll
    for (int m = 0; m < SETSZ; m++) { float e = expf(sc[m] - mx); sc[m] = e; den += e; }
    float inv = 1.0f / den;
    float o[DHEAD];
#pragma unroll
    for (int d = 0; d < DHEAD; d++) o[d] = 0.f;
#pragma unroll
    for (int m = 0; m < SETSZ; m++) {
        float a = sc[m] * inv;
#pragma unroll
        for (int d = 0; d < DHEAD; d++) o[d] += a * vs[hl][m][d];
    }
    __half* op = outb + ((size_t)s * SETSZ + l) * 256 + (size_t)(h0 + hl) * DHEAD;
#pragma unroll
    for (int p = 0; p < 8; p++)
        write4h(op + p * 4,
                make_float4(o[p*4], o[p*4+1], o[p*4+2], o[p*4+3]));
}

// ---------------------------------------------------------------------------
// LayerNorm helpers
// ---------------------------------------------------------------------------
__device__ __forceinline__ float wsum(float v)
{
#pragma unroll
    for (int o = 16; o > 0; o >>= 1) v += __shfl_xor_sync(0xffffffffu, v, o);
    return v;
}

__device__ __forceinline__ void ln8(float4& v0, float4& v1,
                                    const float* __restrict__ g,
                                    const float* __restrict__ b, int lane)
{
    float s  = v0.x + v0.y + v0.z + v0.w + v1.x + v1.y + v1.z + v1.w;
    float ss = v0.x*v0.x + v0.y*v0.y + v0.z*v0.z + v0.w*v0.w
             + v1.x*v1.x + v1.y*v1.y + v1.z*v1.z + v1.w*v1.w;
    s = wsum(s); ss = wsum(ss);
    float mean = s * (1.0f / 256.0f);
    float var  = ss * (1.0f / 256.0f) - mean * mean;
    float inv  = rsqrtf(fmaxf(var, 0.0f) + 1e-5f);
    float4 G0 = ((const float4*)g)[lane];
    float4 G1 = ((const float4*)g)[lane + 32];
    float4 B0 = ((const float4*)b)[lane];
    float4 B1 = ((const float4*)b)[lane + 32];
    v0.x = (v0.x - mean) * inv * G0.x + B0.x;
    v0.y = (v0.y - mean) * inv * G0.y + B0.y;
    v0.z = (v0.z - mean) * inv * G0.z + B0.z;
    v0.w = (v0.w - mean) * inv * G0.w + B0.w;
    v1.x = (v1.x - mean) * inv * G1.x + B1.x;
    v1.y = (v1.y - mean) * inv * G1.y + B1.y;
    v1.z = (v1.z - mean) * inv * G1.z + B1.z;
    v1.w = (v1.w - mean) * inv * G1.w + B1.w;
}

__device__ __forceinline__ float4 f4add(float4 a, float4 b)
{ return make_float4(a.x + b.x, a.y + b.y, a.z + b.z, a.w + b.w); }

// x1[t] = LN(x[t] + o[j]), t = inds[j]; o fp16; fp32 + fp16 outputs
__global__ __launch_bounds__(256) void ln1_scatter_kernel(
    const float* __restrict__ x, const __half* __restrict__ o,
    const int* __restrict__ inds, const float* __restrict__ g,
    const float* __restrict__ b, float* __restrict__ out,
    __half* __restrict__ outb)
{
    int w = (blockIdx.x << 3) + (threadIdx.x >> 5);
    if (w >= NTOK) return;
    int lane = threadIdx.x & 31;
    int t = inds[w];
    const float4* xr = (const float4*)(x + (size_t)t * 256);
    const __half* orr = o + (size_t)w * 256;
    float4 v0 = f4add(xr[lane],      read4h(orr + lane * 4));
    float4 v1 = f4add(xr[lane + 32], read4h(orr + 128 + lane * 4));
    ln8(v0, v1, g, b, lane);
    ((float4*)(out + (size_t)t * 256))[lane]      = v0;
    ((float4*)(out + (size_t)t * 256))[lane + 32] = v1;
    __half* ar = outb + (size_t)t * 256;
    write4h(ar + lane * 4,       v0);
    write4h(ar + 128 + lane * 4, v1);
}

// xio[t] = LN_enc( LN_2(x1 + ff) + xio );  optionally followed by
// dst[t] = LN_res( result + res[t] )  (block-final fusion, last=1)
__global__ __launch_bounds__(256) void ln2_enc_kernel(
    const float* __restrict__ x1, const __half* __restrict__ ff,
    float* __restrict__ xio,
    const float* __restrict__ g2, const float* __restrict__ b2,
    const float* __restrict__ ge, const float* __restrict__ be,
    const float* __restrict__ res, const float* __restrict__ gr,
    const float* __restrict__ br, float* __restrict__ dst, int last)
{
    int w = (blockIdx.x << 3) + (threadIdx.x >> 5);
    if (w >= NTOK) return;
    int lane = threadIdx.x & 31;
    const float4* r1 = (const float4*)(x1 + (size_t)w * 256);
    const __half* rf = ff + (size_t)w * 256;
    float4* rx = (float4*)(xio + (size_t)w * 256);
    float4 v0 = f4add(r1[lane],      read4h(rf + lane * 4));
    float4 v1 = f4add(r1[lane + 32], read4h(rf + 128 + lane * 4));
    ln8(v0, v1, g2, b2, lane);
    v0 = f4add(v0, rx[lane]);
    v1 = f4add(v1, rx[lane + 32]);
    ln8(v0, v1, ge, be, lane);
    if (last) {
        const float4* rr = (const float4*)(res + (size_t)w * 256);
        v0 = f4add(v0, rr[lane]);
        v1 = f4add(v1, rr[lane + 32]);
        ln8(v0, v1, gr, br, lane);
        ((float4*)(dst + (size_t)w * 256))[lane]      = v0;
        ((float4*)(dst + (size_t)w * 256))[lane + 32] = v1;
    } else {
        rx[lane]      = v0;
        rx[lane + 32] = v1;
    }
}

// ---------------------------------------------------------------------------
// Orchestration
// ---------------------------------------------------------------------------
extern "C" void kernel_launch(void* const* d_in, const int* in_sizes, int n_in,
                              void* d_out, int out_size)
{
    const float* src   = (const float*)d_in[0];
    const float* pos   = (const float*)d_in[1];
    const int*   inds  = (const int*)  d_in[2];
    const void*  masks =               d_in[3];
    const float* ipw   = (const float*)d_in[4];
    const float* ipb   = (const float*)d_in[5];
    const float* oww   = (const float*)d_in[6];
    const float* owb   = (const float*)d_in[7];
    const float* l1w   = (const float*)d_in[8];
    const float* l1b   = (const float*)d_in[9];
    const float* l2w   = (const float*)d_in[10];
    const float* l2b   = (const float*)d_in[11];
    const float* n1g   = (const float*)d_in[12];
    const float* n1b   = (const float*)d_in[13];
    const float* n2g   = (const float*)d_in[14];
    const float* n2b   = (const float*)d_in[15];
    const float* encg  = (const float*)d_in[16];
    const float* encb  = (const float*)d_in[17];
    const float* resg  = (const float*)d_in[18];
    const float* resb  = (const float*)d_in[19];
    float* outp = (float*)d_out;

    char* ws;
    cudaGetSymbolAddress((void**)&ws, g_ws);
    float*  x     = (float*)(ws + OFF_X);
    float*  res   = (float*)(ws + OFF_RES);
    __half* qkph  = (__half*)(ws + OFF_QKPH);
    float*  x1    = (float*)(ws + OFF_QKPH);   // alias: qkph dead after attn
    __half* vh    = (__half*)(ws + OFF_VOF);
    __half* oh    = (__half*)(ws + OFF_VOF);   // alias
    __half* ffh   = (__half*)(ws + OFF_VOF);   // alias
    __half* qkb   = (__half*)(ws + OFF_QKB);
    __half* x1b   = (__half*)(ws + OFF_QKB);   // alias
    __half* featb = (__half*)(ws + OFF_FEB);
    __half* attnb = (__half*)(ws + OFF_FEB);   // alias
    __half* hb    = (__half*)(ws + OFF_HB);
    __half* ipwb  = (__half*)(ws + OFF_WIP);
    __half* owwb  = (__half*)(ws + OFF_WOW);
    __half* l1wb  = (__half*)(ws + OFF_WL1);
    __half* l2wb  = (__half*)(ws + OFF_WL2);

    cudaFuncSetAttribute(gemm_fp16_kernel,
                         cudaFuncAttributeMaxDynamicSharedMemorySize, GSMEM);

    const size_t xbytes = (size_t)NTOK * CDIM * sizeof(float);
    const int gM = (NTOK + 127) / 128;   // 2049

    detect_mask_kernel<<<1, 256>>>((const unsigned int*)masks,
                                   (2 * 2 * NSETS * SETSZ) / 4);
    wconv_kernel<<<(4 * 768 * 256 + 255) / 256, 256>>>(ipw, ipwb, 4 * 768 * 256);
    wconv_kernel<<<(4 * 256 * 256 + 255) / 256, 256>>>(oww, owwb, 4 * 256 * 256);
    wconv_kernel<<<(4 * 1024 * 256 + 255) / 256, 256>>>(l1w, l1wb, 4 * 1024 * 256);
    wconv_kernel<<<(4 * 256 * 1024 + 255) / 256, 256>>>(l2w, l2wb, 4 * 256 * 1024);

    cudaMemcpyAsync(x, src, xbytes, cudaMemcpyDeviceToDevice);

    for (int blk = 0; blk < 2; blk++) {
        cudaMemcpyAsync(res, x, xbytes, cudaMemcpyDeviceToDevice);
        for (int i = 0; i < 2; i++) {
            int lid = blk * 2 + i;
            const int* ip = inds + (size_t)lid * NSETS * SETSZ;
            int moff = lid * NSETS * SETSZ;
            const float* pp = pos + (size_t)lid * NTOK * CDIM;

            gather_kernel<<<(NTOK * 64 + 255) / 256, 256>>>(
                x, pp, ip, qkb, featb);

            // in-proj QK (N=512) and V (N=256)
            gemm_fp16_kernel<<<dim3(4, gM), 256, GSMEM>>>(
                qkb, 256, ipwb + (size_t)lid * 768 * 256,
                ipb + (size_t)lid * 768, qkph, NTOK, 512, 0);
            gemm_fp16_kernel<<<dim3(2, gM), 256, GSMEM>>>(
                featb, 256, ipwb + (size_t)lid * 768 * 256 + (size_t)512 * 256,
                ipb + (size_t)lid * 768 + 512, vh, NTOK, 256, 0);

            attn_kernel<<<dim3(NSETS, 2), 144>>>(qkph, vh, masks, moff, attnb);

            gemm_fp16_kernel<<<dim3(2, gM), 256, GSMEM>>>(
                attnb, 256, owwb + (size_t)lid * 256 * 256,
                owb + (size_t)lid * 256, oh, NTOK, 256, 0);

            ln1_scatter_kernel<<<(NTOK + 7) / 8, 256>>>(
                x, oh, ip, n1g + (size_t)lid * 256, n1b + (size_t)lid * 256,
                x1, x1b);

            gemm_fp16_kernel<<<dim3(8, gM), 256, GSMEM>>>(
                x1b, 256, l1wb + (size_t)lid * 1024 * 256,
                l1b + (size_t)lid * 1024, hb, NTOK, 1024, 1);
            gemm_fp16_kernel<<<dim3(2, gM), 256, GSMEM>>>(
                hb, 1024, l2wb + (size_t)lid * 256 * 1024,
                l2b + (size_t)lid * 256, ffh, NTOK, 256, 0);

            int last = (i == 1);
            float* dst = (blk == 1) ? outp : x;
            ln2_enc_kernel<<<(NTOK + 7) / 8, 256>>>(
                x1, ffh, x,
                n2g + (size_t)lid * 256, n2b + (size_t)lid * 256,
                encg + (size_t)lid * 256, encb + (size_t)lid * 256,
                res, resg + (size_t)blk * 256, resb + (size_t)blk * 256,
                dst, last);
        }
    }
}

// round 15
// speedup vs baseline: 1.0879x; 1.0066x over previous
#include <cuda_runtime.h>
#include <cuda_fp16.h>
#include <mma.h>
#include <cstdint>
#include <cmath>

using namespace nvcuda;

#define NTOK   262152
#define CDIM   256
#define NSETS  7282
#define SETSZ  36
#define NHEAD  8
#define DHEAD  32
#define DFFN   1024

// ---------------------------------------------------------------------------
// Workspace (single symbol, < 4GB). ~2.0 GB.
// Aliases (stream-order safe):
//   x1 (fp32) aliases qkph (fp16 512/tok; both NTOK*1024 bytes)
//   vh == oh == ffh (fp16, each dead before next writer)
//   x1b == qkb, attnb == featb
// ---------------------------------------------------------------------------
#define SZ_C   ((size_t)NTOK * 256 * 4)     // 268MB (fp32 256/tok)
#define SZ_H   ((size_t)NTOK * 256 * 2)     // 134MB (fp16 256/tok)
#define OFF_X    ((size_t)0)
#define OFF_RES  (OFF_X    + SZ_C)
#define OFF_QKPH (OFF_RES  + SZ_C)          // fp16 NTOK x 512; x1 fp32 aliases
#define OFF_VOF  (OFF_QKPH + SZ_C)          // fp16 vh / oh / ffh
#define OFF_QKB  (OFF_VOF  + SZ_H)          // fp16 (x1b aliases)
#define OFF_FEB  (OFF_QKB  + SZ_H)          // fp16 (attnb aliases)
#define OFF_HB   (OFF_FEB  + SZ_H)          // fp16 NTOK x 1024
#define OFF_WIP  (OFF_HB   + (size_t)NTOK * 1024 * 2)
#define OFF_WOW  (OFF_WIP + (size_t)4*768*256*2)
#define OFF_WL1  (OFF_WOW + (size_t)4*256*256*2)
#define OFF_WL2  (OFF_WL1 + (size_t)4*1024*256*2)
#define WS_TOT   (OFF_WL2 + (size_t)4*256*1024*2)

__device__ __align__(256) char g_ws[WS_TOT];
__device__ int g_mask_mode;

// ---------------------------------------------------------------------------
// Helpers
// ---------------------------------------------------------------------------
__device__ __forceinline__ uint32_t smem_u32(const void* p) {
    uint32_t a;
    asm("{ .reg .u64 t; cvta.to.shared.u64 t, %1; cvt.u32.u64 %0, t; }"
        : "=r"(a) : "l"(p));
    return a;
}
__device__ __forceinline__ void cp16(uint32_t dst, const void* src, int sz) {
    asm volatile("cp.async.cg.shared.global [%0], [%1], 16, %2;"
                 :: "r"(dst), "l"(src), "r"(sz) : "memory");
}
#define CP_COMMIT() asm volatile("cp.async.commit_group;" ::: "memory")
#define CP_WAIT1()  asm volatile("cp.async.wait_group 1;" ::: "memory")
#define CP_WAIT0()  asm volatile("cp.async.wait_group 0;" ::: "memory")

__device__ __forceinline__ uint32_t pack2h(float a, float b) {
    __half2 h;
    h.x = __float2half_rn(a); h.y = __float2half_rn(b);
    return *reinterpret_cast<uint32_t*>(&h);
}
__device__ __forceinline__ void write4h(__half* p, float4 v) {
    *(uint2*)p = make_uint2(pack2h(v.x, v.y), pack2h(v.z, v.w));
}
__device__ __forceinline__ float4 read4h(const __half* p) {
    const __half2* h = (const __half2*)p;
    float2 a = __half22float2(h[0]);
    float2 b = __half22float2(h[1]);
    return make_float4(a.x, a.y, b.x, b.y);
}

// ---------------------------------------------------------------------------
// Weight converter: fp32 -> plain fp16
// ---------------------------------------------------------------------------
__global__ __launch_bounds__(256) void wconv_kernel(
    const float* __restrict__ src, __half* __restrict__ dst, int n)
{
    int idx = blockIdx.x * 256 + threadIdx.x;
    if (idx >= n) return;
    dst[idx] = __float2half_rn(src[idx]);
}

// ---------------------------------------------------------------------------
// Mask dtype detector
// ---------------------------------------------------------------------------
__global__ void detect_mask_kernel(const unsigned int* __restrict__ w, int nwords)
{
    __shared__ int f32f, u8f;
    if (threadIdx.x == 0) { f32f = 0; u8f = 0; }
    __syncthreads();
    int lf = 0, lu = 0;
    for (int i = threadIdx.x; i < nwords; i += blockDim.x) {
        unsigned int x = w[i];
        if (x == 0x3F800000u) lf = 1;
        else if (x > 1u)      lu = 1;
    }
    if (lf) f32f = 1;
    if (lu) u8f = 1;
    __syncthreads();
    if (threadIdx.x == 0) g_mask_mode = f32f ? 2 : (u8f ? 1 : 0);
}

// ---------------------------------------------------------------------------
// Gather: fp16 qk (= x[inds]+pos[inds]) and feat (= x[inds])
// ---------------------------------------------------------------------------
__global__ __launch_bounds__(256) void gather_kernel(
    const float* __restrict__ x, const float* __restrict__ pos,
    const int* __restrict__ inds, __half* __restrict__ qkb,
    __half* __restrict__ featb)
{
    int idx = blockIdx.x * 256 + threadIdx.x;
    if (idx >= NTOK * 64) return;
    int j  = idx >> 6;
    int c4 = idx & 63;
    int t  = inds[j];
    float4 xv = ((const float4*)x)  [(size_t)t * 64 + c4];
    float4 pv = ((const float4*)pos)[(size_t)t * 64 + c4];
    float4 q  = make_float4(xv.x + pv.x, xv.y + pv.y, xv.z + pv.z, xv.w + pv.w);
    write4h(featb + (size_t)j * 256 + c4 * 4, xv);
    write4h(qkb   + (size_t)j * 256 + c4 * 4, q);
}

// ---------------------------------------------------------------------------
// fp16 GEMM: C[m,n] = A[m,:] . W[n,:] + bias[n] (+GELU), fp32 acc, fp16 out.
// CTA 128x128, BK=64, 3-stage cp.async, 4 warps (2x2) of 64x64, 2 CTAs/SM.
// Large warp tile: A read by 2 warps, B by 2 warps -> 64KB smem/iter (vs 96).
// ---------------------------------------------------------------------------
#define STAGE_B 36864          // A 128x144B + W 128x144B
#define GSMEM   (3 * STAGE_B)  // 110592; epilogue scratch aliases stages

__global__ __launch_bounds__(128, 2) void gemm_fp16_kernel(
    const __half* __restrict__ A, int KA,
    const __half* __restrict__ W, const float* __restrict__ bias,
    __half* __restrict__ C, int M, int N, int act)
{
    extern __shared__ char smem[];
    const uint32_t sb = smem_u32(smem);
    const int tid  = threadIdx.x;
    const int wid  = tid >> 5;
    const int lane = tid & 31;
    const int wr   = wid >> 1;   // 0..1
    const int wc   = wid & 1;    // 0..1
    const int m0   = blockIdx.y * 128;
    const int n0   = blockIdx.x * 128;
    const int NC   = KA >> 6;

    wmma::fragment<wmma::accumulator, 16, 16, 16, float> acc[4][4];
#pragma unroll
    for (int i = 0; i < 4; i++)
#pragma unroll
        for (int j = 0; j < 4; j++) wmma::fill_fragment(acc[i][j], 0.0f);

    auto load_stage = [&](int slot, int c) {
        const int k0 = c << 6;
        const uint32_t base = sb + slot * STAGE_B;
#pragma unroll
        for (int it = 0; it < 8; it++) {
            int i  = tid + it * 128;      // 0..1023
            int r  = i >> 3;              // row 0..127
            int ch = i & 7;               // 16B chunk 0..7
            int gr = m0 + r;
            const __half* sa =
                A + (size_t)(gr < M ? gr : M - 1) * KA + k0 + ch * 8;
            cp16(base + r * 144 + ch * 16, sa, gr < M ? 16 : 0);
            const __half* sw = W + (size_t)(n0 + r) * KA + k0 + ch * 8;
            cp16(base + 18432 + r * 144 + ch * 16, sw, 16);
        }
    };

    load_stage(0, 0); CP_COMMIT();
    load_stage(1, 1); CP_COMMIT();

    for (int c = 0; c < NC; c++) {
        CP_WAIT1();
        __syncthreads();
        const int slot = c % 3;
        const __half* sA = (const __half*)(smem + slot * STAGE_B);
        const __half* sB = (const __half*)(smem + slot * STAGE_B + 18432);
#pragma unroll
        for (int kk = 0; kk < 4; kk++) {
            wmma::fragment<wmma::matrix_a, 16, 16, 16, __half,
                           wmma::row_major> a[4];
            wmma::fragment<wmma::matrix_b, 16, 16, 16, __half,
                           wmma::col_major> b[4];
#pragma unroll
            for (int i = 0; i < 4; i++)
                wmma::load_matrix_sync(a[i], sA + (wr * 64 + i * 16) * 72 + kk * 16, 72);
#pragma unroll
            for (int j = 0; j < 4; j++)
                wmma::load_matrix_sync(b[j], sB + (wc * 64 + j * 16) * 72 + kk * 16, 72);
#pragma unroll
            for (int i = 0; i < 4; i++)
#pragma unroll
                for (int j = 0; j < 4; j++)
                    wmma::mma_sync(acc[i][j], a[i], b[j], acc[i][j]);
        }
        // safe without a second barrier: slot (c+2)%3 was last read in iter
        // c-1, and every warp passed this iteration's top barrier after that.
        const int cn = c + 2;
        if (cn < NC) load_stage(cn % 3, cn);
        CP_COMMIT();
    }

    CP_WAIT0();
    __syncthreads();

    // epilogue: each warp stages its full 64x64 fp32 tile once (stride 68,
    // conflict-free 16B phases), then each lane emits two rows.
    float* scr = (float*)smem + wid * 64 * 68;
#pragma unroll
    for (int i = 0; i < 4; i++)
#pragma unroll
        for (int j = 0; j < 4; j++)
            wmma::store_matrix_sync(scr + i * 16 * 68 + j * 16, acc[i][j], 68,
                                    wmma::mem_row_major);
    __syncwarp();
    const float* bp = bias + n0 + wc * 64;
#pragma unroll
    for (int rr = 0; rr < 2; rr++) {
        int lrow = lane + rr * 32;
        int gr = m0 + wr * 64 + lrow;
        if (gr < M) {
            const float* row = scr + lrow * 68;
            __half* hp = C + (size_t)gr * N + n0 + wc * 64;
#pragma unroll
            for (int p = 0; p < 4; p++) {
                float v[16];
#pragma unroll
                for (int q = 0; q < 4; q++) {
                    float4 a4 = *(const float4*)(row + p * 16 + q * 4);
                    float4 b4 = *(const float4*)(bp  + p * 16 + q * 4);
                    v[q*4+0] = a4.x + b4.x;
                    v[q*4+1] = a4.y + b4.y;
                    v[q*4+2] = a4.z + b4.z;
                    v[q*4+3] = a4.w + b4.w;
                }
                if (act) {
#pragma unroll
                    for (int e = 0; e < 16; e++)
                        v[e] = 0.5f * v[e] *
                               (1.0f + erff(v[e] * 0.70710678118654752f));
                }
                uint4 o0, o1;
                o0.x = pack2h(v[0],  v[1]);  o0.y = pack2h(v[2],  v[3]);
                o0.z = pack2h(v[4],  v[5]);  o0.w = pack2h(v[6],  v[7]);
                o1.x = pack2h(v[8],  v[9]);  o1.y = pack2h(v[10], v[11]);
                o1.z = pack2h(v[12], v[13]); o1.w = pack2h(v[14], v[15]);
                *(uint4*)(hp + p * 16)     = o0;
                *(uint4*)(hp + p * 16 + 8) = o1;
            }
        }
    }
}

// ---------------------------------------------------------------------------
// Set attention (fp32 math, fp16 in/out)
// ---------------------------------------------------------------------------
__global__ __launch_bounds__(144, 1) void attn_kernel(
    const __half* __restrict__ qkp, const __half* __restrict__ vb,
    const void* __restrict__ maskp, int mask_off,
    __half* __restrict__ outb)
{
    const int s   = blockIdx.x;
    const int h0  = blockIdx.y * 4;
    const int tid = threadIdx.x;
    const int hl  = tid / SETSZ;
    const int l   = tid - hl * SETSZ;

    __shared__ float ks[4][SETSZ][DHEAD];
    __shared__ float vs[4][SETSZ][DHEAD];
    __shared__ float msk[SETSZ];

    if (tid < SETSZ) {
        int gi = mask_off + s * SETSZ + tid;
        int mode = g_mask_mode;
        bool m;
        if (mode == 0)      m = ((const int*)maskp)[gi] != 0;
        else if (mode == 1) m = ((const unsigned char*)maskp)[gi] != 0;
        else                m = ((const float*)maskp)[gi] != 0.0f;
        msk[tid] = m ? -INFINITY : 0.0f;
    }
    for (int idx = tid; idx < 4 * SETSZ * DHEAD; idx += 144) {
        int d  = idx & (DHEAD - 1);
        int m  = (idx >> 5) % SETSZ;
        int hh = idx / (DHEAD * SETSZ);
        size_t row = (size_t)s * SETSZ + m;
        ks[hh][m][d] = __half2float(qkp[row * 512 + 256 + (size_t)(h0 + hh) * DHEAD + d]);
        vs[hh][m][d] = __half2float(vb [row * 256 +       (size_t)(h0 + hh) * DHEAD + d]);
    }
    __syncthreads();

    float q[DHEAD];
    {
        const __half2* qr = (const __half2*)(qkp + ((size_t)s * SETSZ + l) * 512
                                             + (size_t)(h0 + hl) * DHEAD);
#pragma unroll
        for (int p = 0; p < 16; p++) {
            float2 f = __half22float2(qr[p]);
            q[2 * p] = f.x; q[2 * p + 1] = f.y;
        }
    }
    const float scale = 0.17677669529663687f;
    float sc[SETSZ];
    float mx = -INFINITY;
#pragma unroll
    for (int m = 0; m < SETSZ; m++) {
        float a = 0.f;
#pragma unroll
        for (int d = 0; d < DHEAD; d++) a += q[d] * ks[hl][m][d];
        a = a * scale + msk[m];
        sc[m] = a;
        mx = fmaxf(mx, a);
    }
    float den = 0.f;
#pragma unroll
    for (int m = 0; m < SETSZ; m++) { float e = expf(sc[m] - mx); sc[m] = e; den += e; }
    float inv = 1.0f / den;
    float o[DHEAD];
#pragma unroll
    for (int d = 0; d < DHEAD; d++) o[d] = 0.f;
#pragma unroll
    for (int m = 0; m < SETSZ; m++) {
        float a = sc[m] * inv;
#pragma unroll
        for (int d = 0; d < DHEAD; d++) o[d] += a * vs[hl][m][d];
    }
    __half* op = outb + ((size_t)s * SETSZ + l) * 256 + (size_t)(h0 + hl) * DHEAD;
#pragma unroll
    for (int p = 0; p < 8; p++)
        write4h(op + p * 4,
                make_float4(o[p*4], o[p*4+1], o[p*4+2], o[p*4+3]));
}

// ---------------------------------------------------------------------------
// LayerNorm helpers
// ---------------------------------------------------------------------------
__device__ __forceinline__ float wsum(float v)
{
#pragma unroll
    for (int o = 16; o > 0; o >>= 1) v += __shfl_xor_sync(0xffffffffu, v, o);
    return v;
}

__device__ __forceinline__ void ln8(float4& v0, float4& v1,
                                    const float* __restrict__ g,
                                    const float* __restrict__ b, int lane)
{
    float s  = v0.x + v0.y + v0.z + v0.w + v1.x + v1.y + v1.z + v1.w;
    float ss = v0.x*v0.x + v0.y*v0.y + v0.z*v0.z + v0.w*v0.w
             + v1.x*v1.x + v1.y*v1.y + v1.z*v1.z + v1.w*v1.w;
    s = wsum(s); ss = wsum(ss);
    float mean = s * (1.0f / 256.0f);
    float var  = ss * (1.0f / 256.0f) - mean * mean;
    float inv  = rsqrtf(fmaxf(var, 0.0f) + 1e-5f);
    float4 G0 = ((const float4*)g)[lane];
    float4 G1 = ((const float4*)g)[lane + 32];
    float4 B0 = ((const float4*)b)[lane];
    float4 B1 = ((const float4*)b)[lane + 32];
    v0.x = (v0.x - mean) * inv * G0.x + B0.x;
    v0.y = (v0.y - mean) * inv * G0.y + B0.y;
    v0.z = (v0.z - mean) * inv * G0.z + B0.z;
    v0.w = (v0.w - mean) * inv * G0.w + B0.w;
    v1.x = (v1.x - mean) * inv * G1.x + B1.x;
    v1.y = (v1.y - mean) * inv * G1.y + B1.y;
    v1.z = (v1.z - mean) * inv * G1.z + B1.z;
    v1.w = (v1.w - mean) * inv * G1.w + B1.w;
}

__device__ __forceinline__ float4 f4add(float4 a, float4 b)
{ return make_float4(a.x + b.x, a.y + b.y, a.z + b.z, a.w + b.w); }

// x1[t] = LN(x[t] + o[j]), t = inds[j]; o fp16; fp32 + fp16 outputs
__global__ __launch_bounds__(256) void ln1_scatter_kernel(
    const float* __restrict__ x, const __half* __restrict__ o,
    const int* __restrict__ inds, const float* __restrict__ g,
    const float* __restrict__ b, float* __restrict__ out,
    __half* __restrict__ outb)
{
    int w = (blockIdx.x << 3) + (threadIdx.x >> 5);
    if (w >= NTOK) return;
    int lane = threadIdx.x & 31;
    int t = inds[w];
    const float4* xr = (const float4*)(x + (size_t)t * 256);
    const __half* orr = o + (size_t)w * 256;
    float4 v0 = f4add(xr[lane],      read4h(orr + lane * 4));
    float4 v1 = f4add(xr[lane + 32], read4h(orr + 128 + lane * 4));
    ln8(v0, v1, g, b, lane);
    ((float4*)(out + (size_t)t * 256))[lane]      = v0;
    ((float4*)(out + (size_t)t * 256))[lane + 32] = v1;
    __half* ar = outb + (size_t)t * 256;
    write4h(ar + lane * 4,       v0);
    write4h(ar + 128 + lane * 4, v1);
}

// xio[t] = LN_enc( LN_2(x1 + ff) + xio );  optionally followed by
// dst[t] = LN_res( result + res[t] )  (block-final fusion, last=1)
__global__ __launch_bounds__(256) void ln2_enc_kernel(
    const float* __restrict__ x1, const __half* __restrict__ ff,
    float* __restrict__ xio,
    const float* __restrict__ g2, const float* __restrict__ b2,
    const float* __restrict__ ge, const float* __restrict__ be,
    const float* __restrict__ res, const float* __restrict__ gr,
    const float* __restrict__ br, float* __restrict__ dst, int last)
{
    int w = (blockIdx.x << 3) + (threadIdx.x >> 5);
    if (w >= NTOK) return;
    int lane = threadIdx.x & 31;
    const float4* r1 = (const float4*)(x1 + (size_t)w * 256);
    const __half* rf = ff + (size_t)w * 256;
    float4* rx = (float4*)(xio + (size_t)w * 256);
    float4 v0 = f4add(r1[lane],      read4h(rf + lane * 4));
    float4 v1 = f4add(r1[lane + 32], read4h(rf + 128 + lane * 4));
    ln8(v0, v1, g2, b2, lane);
    v0 = f4add(v0, rx[lane]);
    v1 = f4add(v1, rx[lane + 32]);
    ln8(v0, v1, ge, be, lane);
    if (last) {
        const float4* rr = (const float4*)(res + (size_t)w * 256);
        v0 = f4add(v0, rr[lane]);
        v1 = f4add(v1, rr[lane + 32]);
        ln8(v0, v1, gr, br, lane);
        ((float4*)(dst + (size_t)w * 256))[lane]      = v0;
        ((float4*)(dst + (size_t)w * 256))[lane + 32] = v1;
    } else {
        rx[lane]      = v0;
        rx[lane + 32] = v1;
    }
}

// ---------------------------------------------------------------------------
// Orchestration
// ---------------------------------------------------------------------------
extern "C" void kernel_launch(void* const* d_in, const int* in_sizes, int n_in,
                              void* d_out, int out_size)
{
    const float* src   = (const float*)d_in[0];
    const float* pos   = (const float*)d_in[1];
    const int*   inds  = (const int*)  d_in[2];
    const void*  masks =               d_in[3];
    const float* ipw   = (const float*)d_in[4];
    const float* ipb   = (const float*)d_in[5];
    const float* oww   = (const float*)d_in[6];
    const float* owb   = (const float*)d_in[7];
    const float* l1w   = (const float*)d_in[8];
    const float* l1b   = (const float*)d_in[9];
    const float* l2w   = (const float*)d_in[10];
    const float* l2b   = (const float*)d_in[11];
    const float* n1g   = (const float*)d_in[12];
    const float* n1b   = (const float*)d_in[13];
    const float* n2g   = (const float*)d_in[14];
    const float* n2b   = (const float*)d_in[15];
    const float* encg  = (const float*)d_in[16];
    const float* encb  = (const float*)d_in[17];
    const float* resg  = (const float*)d_in[18];
    const float* resb  = (const float*)d_in[19];
    float* outp = (float*)d_out;

    char* ws;
    cudaGetSymbolAddress((void**)&ws, g_ws);
    float*  x     = (float*)(ws + OFF_X);
    float*  res   = (float*)(ws + OFF_RES);
    __half* qkph  = (__half*)(ws + OFF_QKPH);
    float*  x1    = (float*)(ws + OFF_QKPH);   // alias: qkph dead after attn
    __half* vh    = (__half*)(ws + OFF_VOF);
    __half* oh    = (__half*)(ws + OFF_VOF);   // alias
    __half* ffh   = (__half*)(ws + OFF_VOF);   // alias
    __half* qkb   = (__half*)(ws + OFF_QKB);
    __half* x1b   = (__half*)(ws + OFF_QKB);   // alias
    __half* featb = (__half*)(ws + OFF_FEB);
    __half* attnb = (__half*)(ws + OFF_FEB);   // alias
    __half* hb    = (__half*)(ws + OFF_HB);
    __half* ipwb  = (__half*)(ws + OFF_WIP);
    __half* owwb  = (__half*)(ws + OFF_WOW);
    __half* l1wb  = (__half*)(ws + OFF_WL1);
    __half* l2wb  = (__half*)(ws + OFF_WL2);

    cudaFuncSetAttribute(gemm_fp16_kernel,
                         cudaFuncAttributeMaxDynamicSharedMemorySize, GSMEM);

    const size_t xbytes = (size_t)NTOK * CDIM * sizeof(float);
    const int gM = (NTOK + 127) / 128;   // 2049

    detect_mask_kernel<<<1, 256>>>((const unsigned int*)masks,
                                   (2 * 2 * NSETS * SETSZ) / 4);
    wconv_kernel<<<(4 * 768 * 256 + 255) / 256, 256>>>(ipw, ipwb, 4 * 768 * 256);
    wconv_kernel<<<(4 * 256 * 256 + 255) / 256, 256>>>(oww, owwb, 4 * 256 * 256);
    wconv_kernel<<<(4 * 1024 * 256 + 255) / 256, 256>>>(l1w, l1wb, 4 * 1024 * 256);
    wconv_kernel<<<(4 * 256 * 1024 + 255) / 256, 256>>>(l2w, l2wb, 4 * 256 * 1024);

    cudaMemcpyAsync(x, src, xbytes, cudaMemcpyDeviceToDevice);

    for (int blk = 0; blk < 2; blk++) {
        cudaMemcpyAsync(res, x, xbytes, cudaMemcpyDeviceToDevice);
        for (int i = 0; i < 2; i++) {
            int lid = blk * 2 + i;
            const int* ip = inds + (size_t)lid * NSETS * SETSZ;
            int moff = lid * NSETS * SETSZ;
            const float* pp = pos + (size_t)lid * NTOK * CDIM;

            gather_kernel<<<(NTOK * 64 + 255) / 256, 256>>>(
                x, pp, ip, qkb, featb);

            // in-proj QK (N=512) and V (N=256)
            gemm_fp16_kernel<<<dim3(4, gM), 128, GSMEM>>>(
                qkb, 256, ipwb + (size_t)lid * 768 * 256,
                ipb + (size_t)lid * 768, qkph, NTOK, 512, 0);
            gemm_fp16_kernel<<<dim3(2, gM), 128, GSMEM>>>(
                featb, 256, ipwb + (size_t)lid * 768 * 256 + (size_t)512 * 256,
                ipb + (size_t)lid * 768 + 512, vh, NTOK, 256, 0);

            attn_kernel<<<dim3(NSETS, 2), 144>>>(qkph, vh, masks, moff, attnb);

            gemm_fp16_kernel<<<dim3(2, gM), 128, GSMEM>>>(
                attnb, 256, owwb + (size_t)lid * 256 * 256,
                owb + (size_t)lid * 256, oh, NTOK, 256, 0);

            ln1_scatter_kernel<<<(NTOK + 7) / 8, 256>>>(
                x, oh, ip, n1g + (size_t)lid * 256, n1b + (size_t)lid * 256,
                x1, x1b);

            gemm_fp16_kernel<<<dim3(8, gM), 128, GSMEM>>>(
                x1b, 256, l1wb + (size_t)lid * 1024 * 256,
                l1b + (size_t)lid * 1024, hb, NTOK, 1024, 1);
            gemm_fp16_kernel<<<dim3(2, gM), 128, GSMEM>>>(
                hb, 1024, l2wb + (size_t)lid * 256 * 1024,
                l2b + (size_t)lid * 256, ffh, NTOK, 256, 0);

            int last = (i == 1);
            float* dst = (blk == 1) ? outp : x;
            ln2_enc_kernel<<<(NTOK + 7) / 8, 256>>>(
                x1, ffh, x,
                n2g + (size_t)lid * 256, n2b + (size_t)lid * 256,
                encg + (size_t)lid * 256, encb + (size_t)lid * 256,
                res, resg + (size_t)blk * 256, resb + (size_t)blk * 256,
                dst, last);
        }
    }
}